// round 2
// baseline (speedup 1.0000x reference)
#include <cuda_runtime.h>
#include <cuda_bf16.h>

#define BB   16
#define CIN  512
#define COUT 512
#define HH   64
#define WW   64
#define SDIM 512
#define KK   3

#define CONV_SCALE 0.014731391274719737f   /* 1/sqrt(512*9) */
#define MOD_SCALE  0.04419417382415922f    /* 1/sqrt(512)   */
#define EPS        1e-8f

#define CO_TILE 64
#define HT      4

// Scratch (allocation-free rule: __device__ globals)
__device__ float g_s[BB * CIN];                 // modulation scales s[b][ci]
__device__ float g_demod[BB * COUT];            // demod[b][co]
__device__ float g_wt[(size_t)CIN * COUT * 9];  // weight transposed [ci][co][k], pre-scaled by CONV_SCALE

// ---------------------------------------------------------------------------
// Kernel 1: s[b][ci] = style[b] . (mod_weight[ci] * MOD_SCALE) + mod_bias[ci]
// grid = B, block = 512 (one thread per ci)
// ---------------------------------------------------------------------------
__global__ void k_style(const float* __restrict__ style,
                        const float* __restrict__ mw,
                        const float* __restrict__ mb) {
    __shared__ float st[SDIM];
    int b = blockIdx.x;
    int t = threadIdx.x;
    st[t] = style[b * SDIM + t];
    __syncthreads();
    const float4* wrow = (const float4*)(mw + (size_t)t * SDIM);
    const float4* srow = (const float4*)st;
    float acc = 0.f;
#pragma unroll 8
    for (int j = 0; j < SDIM / 4; j++) {
        float4 w4 = wrow[j];
        float4 s4 = srow[j];
        acc += w4.x * s4.x + w4.y * s4.y + w4.z * s4.z + w4.w * s4.w;
    }
    g_s[b * CIN + t] = acc * MOD_SCALE + mb[t];
}

// ---------------------------------------------------------------------------
// Kernel 2: transpose weight [co][ci][k] -> [ci][co][k], fold in CONV_SCALE
// ---------------------------------------------------------------------------
__global__ void k_transpose(const float* __restrict__ w) {
    int idx = blockIdx.x * blockDim.x + threadIdx.x;
    const int total = CIN * COUT * 9;
    if (idx >= total) return;
    int k  = idx % 9;
    int co = (idx / 9) % COUT;
    int ci = idx / (9 * COUT);
    g_wt[idx] = CONV_SCALE * w[((size_t)co * CIN + ci) * 9 + k];
}

// ---------------------------------------------------------------------------
// Kernel 3: demod[b][co] = rsqrt(CS^2 * sum_ci s[b][ci]^2 * (sum_k W[co][ci][k]^2) + eps)
// grid = COUT, block = 256
// ---------------------------------------------------------------------------
__global__ void k_demod(const float* __restrict__ w) {
    int co = blockIdx.x;
    int t  = threadIdx.x;
    float acc[BB];
#pragma unroll
    for (int b = 0; b < BB; b++) acc[b] = 0.f;

    for (int ci = t; ci < CIN; ci += 256) {
        const float* wp = w + ((size_t)co * CIN + ci) * 9;
        float wsq = 0.f;
#pragma unroll
        for (int i = 0; i < 9; i++) wsq += wp[i] * wp[i];
#pragma unroll
        for (int b = 0; b < BB; b++) {
            float sv = g_s[b * CIN + ci];
            acc[b] += wsq * sv * sv;
        }
    }

    __shared__ float red[BB][257];
#pragma unroll
    for (int b = 0; b < BB; b++) red[b][t] = acc[b];
    __syncthreads();
    for (int off = 128; off > 0; off >>= 1) {
        if (t < off) {
#pragma unroll
            for (int b = 0; b < BB; b++) red[b][t] += red[b][t + off];
        }
        __syncthreads();
    }
    if (t < BB) {
        float v = red[t][0];
        g_demod[t * COUT + co] = rsqrtf(CONV_SCALE * CONV_SCALE * v + EPS);
    }
}

// ---------------------------------------------------------------------------
// Kernel 4: the conv.  out[b][co][h][w] = demod * conv(x*s, wt)
// Block tile: 64 co x 4 h x 64 w, one b.  256 threads, thread tile 8co x (2h x 4w).
// Warp w covers co = co0 + warp*8 .. +7 (A-frag loads are warp-broadcast).
// Lane: tx = lane&15 -> w base (w = tx + c*16, conflict-free stride-1 LDS),
//       hs = lane>>4 -> row select (xs row pitch 80 => halves 16 banks apart).
// ---------------------------------------------------------------------------
__global__ __launch_bounds__(256, 1) void k_conv(const float* __restrict__ x,
                                                 float* __restrict__ out) {
    __shared__ float xs[6][80];        // rows h0-1..h0+4, cols -1..64 at index 0..65
    __shared__ float ws[CO_TILE][9];   // weights for current ci

    int ht  = blockIdx.x;              // 16 h-tiles
    int cot = blockIdx.y;              // 8 co-tiles
    int b   = blockIdx.z;              // 16 batches
    int h0  = ht * HT;
    int co0 = cot * CO_TILE;

    int tid  = threadIdx.x;
    int warp = tid >> 5;
    int lane = tid & 31;
    int tx   = lane & 15;
    int hs   = lane >> 4;

    float acc[8][8];
#pragma unroll
    for (int m = 0; m < 8; m++)
#pragma unroll
        for (int n = 0; n < 8; n++) acc[m][n] = 0.f;

    const float* xb = x + (size_t)b * CIN * HH * WW;

    for (int ci = 0; ci < CIN; ci++) {
        __syncthreads();
        // weights: 576 contiguous floats
        const float* wsrc = g_wt + ((size_t)ci * COUT + co0) * 9;
        for (int i = tid; i < CO_TILE * 9; i += 256) ((float*)ws)[i] = wsrc[i];
        // x patch 6 x 66 (zero-padded borders), scaled by s[b][ci]
        float sv = g_s[b * CIN + ci];
        const float* xc = xb + (size_t)ci * HH * WW;
        for (int i = tid; i < 6 * 66; i += 256) {
            int r = i / 66, c = i - r * 66;
            int hh = h0 - 1 + r;
            int wc = c - 1;
            float v = 0.f;
            if ((unsigned)hh < HH && (unsigned)wc < WW) v = xc[hh * WW + wc] * sv;
            xs[r][c] = v;
        }
        __syncthreads();

#pragma unroll
        for (int ky = 0; ky < 3; ky++) {
#pragma unroll
            for (int kx = 0; kx < 3; kx++) {
                float bx[8];
#pragma unroll
                for (int r = 0; r < 2; r++)
#pragma unroll
                    for (int c = 0; c < 4; c++)
                        bx[r * 4 + c] = xs[hs + r * 2 + ky][tx + c * 16 + kx];
                float aw[8];
#pragma unroll
                for (int m = 0; m < 8; m++) aw[m] = ws[warp * 8 + m][ky * 3 + kx];
#pragma unroll
                for (int m = 0; m < 8; m++)
#pragma unroll
                    for (int n = 0; n < 8; n++)
                        acc[m][n] = fmaf(aw[m], bx[n], acc[m][n]);
            }
        }
    }

    // epilogue: apply demod, write out
#pragma unroll
    for (int m = 0; m < 8; m++) {
        int co = co0 + warp * 8 + m;
        float dm = g_demod[b * COUT + co];
        float* op = out + ((size_t)b * COUT + co) * HH * WW;
#pragma unroll
        for (int r = 0; r < 2; r++) {
            int hh = h0 + hs + r * 2;
#pragma unroll
            for (int c = 0; c < 4; c++) {
                int wcol = tx + c * 16;
                op[hh * WW + wcol] = acc[m][r * 4 + c] * dm;
            }
        }
    }
}

// ---------------------------------------------------------------------------
extern "C" void kernel_launch(void* const* d_in, const int* in_sizes, int n_in,
                              void* d_out, int out_size) {
    const float* x      = (const float*)d_in[0];  // [16,512,64,64]
    const float* style  = (const float*)d_in[1];  // [16,512]
    const float* weight = (const float*)d_in[2];  // [1,512,512,3,3]
    const float* mw     = (const float*)d_in[3];  // [512,512]
    const float* mb     = (const float*)d_in[4];  // [512]
    float* out          = (float*)d_out;          // [16,512,64,64]

    k_style<<<BB, SDIM>>>(style, mw, mb);

    {
        int total = CIN * COUT * 9;
        k_transpose<<<(total + 255) / 256, 256>>>(weight);
    }

    k_demod<<<COUT, 256>>>(weight);

    dim3 grid(16 /*h tiles*/, 8 /*co tiles*/, BB);
    k_conv<<<grid, 256>>>(x, out);
}

// round 4
// speedup vs baseline: 3.5052x; 3.5052x over previous
#include <cuda_runtime.h>
#include <cuda_bf16.h>
#include <cstdint>

#define BB   16
#define CIN  512
#define COUT 512
#define HH   64
#define WW   64
#define SDIM 512

#define CONV_SCALE 0.014731391274719737f   /* 1/sqrt(512*9) */
#define MOD_SCALE  0.04419417382415922f    /* 1/sqrt(512)   */
#define EPS        1e-8f

// ---------------------------------------------------------------------------
// Device scratch (allocation-free rule: __device__ globals, zero-initialized)
// ---------------------------------------------------------------------------
__device__ float g_s[BB * CIN];                 // modulation scales s[b][ci]
__device__ float g_demod[BB * COUT];            // demod[b][co]
// Padded NHWC modulated input, bf16 split: [b][66][66][hi:512 | lo:512]
// Borders (row/col 0 and 65) never written -> stay zero (static zero-init).
__device__ __nv_bfloat16 g_xcat[(size_t)BB * 66 * 66 * 1024];
// Weights, bf16 split: [k(9)][co(512)][hi:512 | lo:512], pre-scaled by CONV_SCALE
__device__ __nv_bfloat16 g_wcat[(size_t)9 * COUT * 1024];

// ---------------------------------------------------------------------------
// PTX helpers (base ISA only: cp.async / ldmatrix / mma.sync -- no 'a' features)
// ---------------------------------------------------------------------------
__device__ __forceinline__ uint32_t smem_u32(const void* p) {
    uint32_t a;
    asm("{ .reg .u64 t; cvta.to.shared.u64 t, %1; cvt.u32.u64 %0, t; }" : "=r"(a) : "l"(p));
    return a;
}
__device__ __forceinline__ void cpa16(uint32_t dst, const void* src) {
    asm volatile("cp.async.cg.shared.global [%0], [%1], 16;" :: "r"(dst), "l"(src));
}
#define CP_COMMIT() asm volatile("cp.async.commit_group;" ::: "memory")
template <int N>
__device__ __forceinline__ void cp_wait() {
    asm volatile("cp.async.wait_group %0;" :: "n"(N) : "memory");
}
__device__ __forceinline__ void ldsm4(uint32_t* r, uint32_t addr) {
    asm volatile("ldmatrix.sync.aligned.m8n8.x4.shared.b16 {%0,%1,%2,%3}, [%4];"
                 : "=r"(r[0]), "=r"(r[1]), "=r"(r[2]), "=r"(r[3]) : "r"(addr));
}
__device__ __forceinline__ void mma16816(float* d, const uint32_t* a,
                                         uint32_t b0, uint32_t b1) {
    asm volatile(
        "mma.sync.aligned.m16n8k16.row.col.f32.bf16.bf16.f32 "
        "{%0,%1,%2,%3}, {%4,%5,%6,%7}, {%8,%9}, {%0,%1,%2,%3};"
        : "+f"(d[0]), "+f"(d[1]), "+f"(d[2]), "+f"(d[3])
        : "r"(a[0]), "r"(a[1]), "r"(a[2]), "r"(a[3]), "r"(b0), "r"(b1));
}

// ---------------------------------------------------------------------------
// Kernel 1: s[b][ci] = style[b] . (mod_weight[ci] * MOD_SCALE) + mod_bias[ci]
// ---------------------------------------------------------------------------
__global__ void k_style(const float* __restrict__ style,
                        const float* __restrict__ mw,
                        const float* __restrict__ mb) {
    __shared__ float st[SDIM];
    int b = blockIdx.x;
    int t = threadIdx.x;
    st[t] = style[b * SDIM + t];
    __syncthreads();
    const float4* wrow = (const float4*)(mw + (size_t)t * SDIM);
    const float4* srow = (const float4*)st;
    float acc = 0.f;
#pragma unroll 8
    for (int j = 0; j < SDIM / 4; j++) {
        float4 w4 = wrow[j];
        float4 s4 = srow[j];
        acc += w4.x * s4.x + w4.y * s4.y + w4.z * s4.z + w4.w * s4.w;
    }
    g_s[b * CIN + t] = acc * MOD_SCALE + mb[t];
}

// ---------------------------------------------------------------------------
// Kernel 2: demod[b][co]
// ---------------------------------------------------------------------------
__global__ void k_demod(const float* __restrict__ w) {
    int co = blockIdx.x;
    int t  = threadIdx.x;
    float acc[BB];
#pragma unroll
    for (int b = 0; b < BB; b++) acc[b] = 0.f;

    for (int ci = t; ci < CIN; ci += 256) {
        const float* wp = w + ((size_t)co * CIN + ci) * 9;
        float wsq = 0.f;
#pragma unroll
        for (int i = 0; i < 9; i++) wsq += wp[i] * wp[i];
#pragma unroll
        for (int b = 0; b < BB; b++) {
            float sv = g_s[b * CIN + ci];
            acc[b] += wsq * sv * sv;
        }
    }

    __shared__ float red[BB][257];
#pragma unroll
    for (int b = 0; b < BB; b++) red[b][t] = acc[b];
    __syncthreads();
    for (int off = 128; off > 0; off >>= 1) {
        if (t < off) {
#pragma unroll
            for (int b = 0; b < BB; b++) red[b][t] += red[b][t + off];
        }
        __syncthreads();
    }
    if (t < BB) {
        float v = red[t][0];
        g_demod[t * COUT + co] = rsqrtf(CONV_SCALE * CONV_SCALE * v + EPS);
    }
}

// ---------------------------------------------------------------------------
// Kernel 3: weights -> bf16 hi/lo split, [k][co][hi|lo], pre-scaled
// ---------------------------------------------------------------------------
__global__ void k_prepw(const float* __restrict__ wt) {
    int co = blockIdx.x, ci = threadIdx.x;
    const float* wp = wt + ((size_t)co * CIN + ci) * 9;
#pragma unroll
    for (int k = 0; k < 9; k++) {
        float v = CONV_SCALE * wp[k];
        __nv_bfloat16 hi = __float2bfloat16(v);
        float lo = v - __bfloat162float(hi);
        size_t base = ((size_t)(k * COUT + co)) * 1024 + ci;
        g_wcat[base]       = hi;
        g_wcat[base + 512] = __float2bfloat16(lo);
    }
}

// ---------------------------------------------------------------------------
// Kernel 4: x -> modulated padded NHWC bf16 hi/lo split
// ---------------------------------------------------------------------------
__global__ void k_prepx(const float* __restrict__ x) {
    int h = blockIdx.x, b = blockIdx.y;
    int tid = threadIdx.x;
    __shared__ float t[32][65];
    __shared__ float sv[32];
    for (int chunk = 0; chunk < 16; chunk++) {
        int ci0 = chunk * 32;
        __syncthreads();
        {
            int r  = tid >> 5;
            int w2 = tid & 31;
#pragma unroll
            for (int rr = 0; rr < 4; rr++) {
                int cl = r * 4 + rr;
                const float* xp = x + (((size_t)b * CIN + ci0 + cl) * HH + h) * WW;
                t[cl][w2]      = xp[w2];
                t[cl][w2 + 32] = xp[w2 + 32];
            }
            if (tid < 32) sv[tid] = g_s[b * CIN + ci0 + tid];
        }
        __syncthreads();
        int ci = tid & 31, wg = tid >> 5;
        float s = sv[ci];
#pragma unroll
        for (int ww = 0; ww < 8; ww++) {
            int w = wg * 8 + ww;
            float v = t[ci][w] * s;
            __nv_bfloat16 hi = __float2bfloat16(v);
            float lo = v - __bfloat162float(hi);
            size_t base = (((size_t)b * 66 + h + 1) * 66 + (w + 1)) * 1024 + ci0 + ci;
            g_xcat[base]       = hi;
            g_xcat[base + 512] = __float2bfloat16(lo);
        }
    }
}

// ---------------------------------------------------------------------------
// Kernel 5: HMMA conv.  GEMM: M=co(128/CTA), N=spatial(128/CTA = 2h x 64w).
// K-loop: 432 iters = 3 passes (hi*whi, lo*whi, hi*wlo) x 9 offsets x 16 ci32.
// A = weights tile [128co x 32k], B = x tile [128sp x 32k], both k-major,
// smem row stride 80B (conflict-free ldmatrix, no swizzle needed).
// 3-stage cp.async ring; 8 warps (4M x 2N), warp tile 32co x 64sp.
// ---------------------------------------------------------------------------
#define ITERS 432
#define STAGE 20480
#define SMEM_SZ (3 * STAGE)

__global__ __launch_bounds__(256, 1) void k_conv_mma(float* __restrict__ out) {
    extern __shared__ char smem[];
    uint32_t sb = smem_u32(smem);

    int tid  = threadIdx.x;
    int lane = tid & 31;
    int warp = tid >> 5;
    int wm   = warp & 3;          // 0..3 -> co
    int wn   = warp >> 2;         // 0..1 -> spatial
    int mBase = wm * 32;
    int nBase = wn * 64;

    int h0  = blockIdx.x * 2;     // 2 output h rows per CTA
    int P0  = blockIdx.x * 128;   // global spatial base (h*64+w)
    int co0 = blockIdx.y * 128;
    int b   = blockIdx.z;

    const char* xb = (const char*)g_xcat;
    const char* wb = (const char*)g_wcat;

    float acc[2][8][4];
#pragma unroll
    for (int i = 0; i < 2; i++)
#pragma unroll
        for (int j = 0; j < 8; j++)
#pragma unroll
            for (int k = 0; k < 4; k++) acc[i][j][k] = 0.f;

    // ---- stage loader: iter -> (pass, offset, ci chunk) ----
    auto load_stage = [&](int it) {
        int s  = it % 3;
        int t  = it / 144;          // split pass
        int o  = (it / 16) % 9;     // ky*3+kx
        int cc = it & 15;           // ci chunk of 32
        int ky = o / 3, kx = o % 3;
        int wcol = ((t == 2) ? 512 : 0) + cc * 32;
        int xcol = ((t == 1) ? 512 : 0) + cc * 32;
        uint32_t As = sb + s * STAGE;
        uint32_t Bs = As + 10240;
        // A: 128 co rows x 64B (4 x 16B)
#pragma unroll
        for (int i = tid; i < 512; i += 256) {
            int rr = i >> 2, c = i & 3;
            size_t off = (((size_t)o * COUT + co0 + rr) * 1024 + wcol) * 2 + (size_t)c * 16;
            cpa16(As + rr * 80 + c * 16, wb + off);
        }
        // B: 128 spatial rows x 64B
#pragma unroll
        for (int i = tid; i < 512; i += 256) {
            int p = i >> 2, c = i & 3;
            int hp = h0 + (p >> 6) + ky;
            int wp = (p & 63) + kx;
            size_t off = ((((size_t)b * 66 + hp) * 66 + wp) * 1024 + xcol) * 2 + (size_t)c * 16;
            cpa16(Bs + p * 80 + c * 16, xb + off);
        }
        CP_COMMIT();
    };

    load_stage(0);
    load_stage(1);

    // per-thread ldmatrix lane addressing (row stride 80B)
    int aRow = mBase + (lane & 15);                 // + mt*16
    int aKof = (lane >> 4) * 16;                    // + ks*32
    int bRow0 = nBase + (lane & 7) + ((lane >> 4) << 3);  // + ng*16
    int bKof = ((lane >> 3) & 1) * 16;              // + ks*32

    for (int it = 0; it < ITERS; it++) {
        if (it == ITERS - 1) cp_wait<0>(); else cp_wait<1>();
        __syncthreads();
        uint32_t As = sb + (it % 3) * STAGE;
        uint32_t Bs = As + 10240;

#pragma unroll
        for (int ks = 0; ks < 2; ks++) {
            uint32_t a[2][4];
#pragma unroll
            for (int mt = 0; mt < 2; mt++)
                ldsm4(a[mt], As + (aRow + mt * 16) * 80 + aKof + ks * 32);
            uint32_t bf[4][4];
#pragma unroll
            for (int ng = 0; ng < 4; ng++)
                ldsm4(bf[ng], Bs + (bRow0 + ng * 16) * 80 + bKof + ks * 32);
#pragma unroll
            for (int mt = 0; mt < 2; mt++)
#pragma unroll
                for (int ng = 0; ng < 4; ng++) {
                    mma16816(acc[mt][ng * 2 + 0], a[mt], bf[ng][0], bf[ng][1]);
                    mma16816(acc[mt][ng * 2 + 1], a[mt], bf[ng][2], bf[ng][3]);
                }
        }

        if (it + 2 < ITERS) load_stage(it + 2);
        __syncthreads();
    }

    // ---- epilogue: demod scale + float2 stores (w-contiguous) ----
#pragma unroll
    for (int mt = 0; mt < 2; mt++) {
#pragma unroll
        for (int r = 0; r < 2; r++) {
            int co = co0 + mBase + mt * 16 + (lane >> 2) + r * 8;
            float dm = g_demod[b * COUT + co];
            float* op = out + (((size_t)b * COUT + co) << 12);
#pragma unroll
            for (int j = 0; j < 8; j++) {
                int n = nBase + (j >> 1) * 16 + (j & 1) * 8 + 2 * (lane & 3);
                float2 v;
                v.x = acc[mt][j][r * 2 + 0] * dm;
                v.y = acc[mt][j][r * 2 + 1] * dm;
                *(float2*)(op + P0 + n) = v;
            }
        }
    }
}

// ---------------------------------------------------------------------------
extern "C" void kernel_launch(void* const* d_in, const int* in_sizes, int n_in,
                              void* d_out, int out_size) {
    const float* x      = (const float*)d_in[0];  // [16,512,64,64]
    const float* style  = (const float*)d_in[1];  // [16,512]
    const float* weight = (const float*)d_in[2];  // [1,512,512,3,3]
    const float* mw     = (const float*)d_in[3];  // [512,512]
    const float* mb     = (const float*)d_in[4];  // [512]
    float* out          = (float*)d_out;          // [16,512,64,64]

    k_style<<<BB, SDIM>>>(style, mw, mb);
    k_prepw<<<COUT, CIN>>>(weight);
    k_demod<<<COUT, 256>>>(weight);
    {
        dim3 g(HH, BB);
        k_prepx<<<g, 256>>>(x);
    }
    cudaFuncSetAttribute(k_conv_mma, cudaFuncAttributeMaxDynamicSharedMemorySize, SMEM_SZ);
    {
        dim3 g(32 /*spatial tiles*/, 4 /*co tiles*/, BB);
        k_conv_mma<<<g, 256, SMEM_SZ>>>(out);
    }
}

// round 6
// speedup vs baseline: 4.7213x; 1.3469x over previous
#include <cuda_runtime.h>
#include <cuda_bf16.h>
#include <cstdint>

#define BB   16
#define CIN  512
#define COUT 512
#define HH   64
#define WW   64
#define SDIM 512

#define CONV_SCALE 0.014731391274719737f   /* 1/sqrt(512*9) */
#define MOD_SCALE  0.04419417382415922f    /* 1/sqrt(512)   */
#define EPS        1e-8f

// ---------------------------------------------------------------------------
// Device scratch (allocation-free rule: __device__ globals, zero-initialized)
// ---------------------------------------------------------------------------
__device__ float g_s[BB * CIN];                 // modulation scales s[b][ci]
__device__ float g_demod[BB * COUT];            // demod[b][co]
// Padded NHWC modulated input, bf16 split: [b][66][66][hi:512 | lo:512]
// Borders (row/col 0 and 65) never written -> stay zero (static zero-init).
__device__ __nv_bfloat16 g_xcat[(size_t)BB * 66 * 66 * 1024];
// Weights, bf16 split: [k(9)][co(512)][hi:512 | lo:512], pre-scaled by CONV_SCALE
__device__ __nv_bfloat16 g_wcat[(size_t)9 * COUT * 1024];

// ---------------------------------------------------------------------------
// PTX helpers (base ISA only: cp.async / ldmatrix / mma.sync)
// ---------------------------------------------------------------------------
__device__ __forceinline__ uint32_t smem_u32(const void* p) {
    uint32_t a;
    asm("{ .reg .u64 t; cvta.to.shared.u64 t, %1; cvt.u32.u64 %0, t; }" : "=r"(a) : "l"(p));
    return a;
}
__device__ __forceinline__ void cpa16(uint32_t dst, const void* src) {
    asm volatile("cp.async.cg.shared.global [%0], [%1], 16;" :: "r"(dst), "l"(src));
}
#define CP_COMMIT() asm volatile("cp.async.commit_group;" ::: "memory")
template <int N>
__device__ __forceinline__ void cp_wait() {
    asm volatile("cp.async.wait_group %0;" :: "n"(N) : "memory");
}
__device__ __forceinline__ void ldsm4(uint32_t* r, uint32_t addr) {
    asm volatile("ldmatrix.sync.aligned.m8n8.x4.shared.b16 {%0,%1,%2,%3}, [%4];"
                 : "=r"(r[0]), "=r"(r[1]), "=r"(r[2]), "=r"(r[3]) : "r"(addr));
}
__device__ __forceinline__ void mma16816(float* d, const uint32_t* a,
                                         uint32_t b0, uint32_t b1) {
    asm volatile(
        "mma.sync.aligned.m16n8k16.row.col.f32.bf16.bf16.f32 "
        "{%0,%1,%2,%3}, {%4,%5,%6,%7}, {%8,%9}, {%0,%1,%2,%3};"
        : "+f"(d[0]), "+f"(d[1]), "+f"(d[2]), "+f"(d[3])
        : "r"(a[0]), "r"(a[1]), "r"(a[2]), "r"(a[3]), "r"(b0), "r"(b1));
}

// ---------------------------------------------------------------------------
// Kernel 1: s[b][ci] = style[b] . (mod_weight[ci] * MOD_SCALE) + mod_bias[ci]
// ---------------------------------------------------------------------------
__global__ void k_style(const float* __restrict__ style,
                        const float* __restrict__ mw,
                        const float* __restrict__ mb) {
    __shared__ float st[SDIM];
    int b = blockIdx.x;
    int t = threadIdx.x;
    st[t] = style[b * SDIM + t];
    __syncthreads();
    const float4* wrow = (const float4*)(mw + (size_t)t * SDIM);
    const float4* srow = (const float4*)st;
    float acc = 0.f;
#pragma unroll 8
    for (int j = 0; j < SDIM / 4; j++) {
        float4 w4 = wrow[j];
        float4 s4 = srow[j];
        acc += w4.x * s4.x + w4.y * s4.y + w4.z * s4.z + w4.w * s4.w;
    }
    g_s[b * CIN + t] = acc * MOD_SCALE + mb[t];
}

// ---------------------------------------------------------------------------
// Kernel 2: demod[b][co]
// ---------------------------------------------------------------------------
__global__ void k_demod(const float* __restrict__ w) {
    int co = blockIdx.x;
    int t  = threadIdx.x;
    float acc[BB];
#pragma unroll
    for (int b = 0; b < BB; b++) acc[b] = 0.f;

    for (int ci = t; ci < CIN; ci += 256) {
        const float* wp = w + ((size_t)co * CIN + ci) * 9;
        float wsq = 0.f;
#pragma unroll
        for (int i = 0; i < 9; i++) wsq += wp[i] * wp[i];
#pragma unroll
        for (int b = 0; b < BB; b++) {
            float sv = g_s[b * CIN + ci];
            acc[b] += wsq * sv * sv;
        }
    }

    __shared__ float red[BB][257];
#pragma unroll
    for (int b = 0; b < BB; b++) red[b][t] = acc[b];
    __syncthreads();
    for (int off = 128; off > 0; off >>= 1) {
        if (t < off) {
#pragma unroll
            for (int b = 0; b < BB; b++) red[b][t] += red[b][t + off];
        }
        __syncthreads();
    }
    if (t < BB) {
        float v = red[t][0];
        g_demod[t * COUT + co] = rsqrtf(CONV_SCALE * CONV_SCALE * v + EPS);
    }
}

// ---------------------------------------------------------------------------
// Kernel 3: weights -> bf16 hi/lo split, [k][co][hi|lo], pre-scaled
// ---------------------------------------------------------------------------
__global__ void k_prepw(const float* __restrict__ wt) {
    int co = blockIdx.x, ci = threadIdx.x;
    const float* wp = wt + ((size_t)co * CIN + ci) * 9;
#pragma unroll
    for (int k = 0; k < 9; k++) {
        float v = CONV_SCALE * wp[k];
        __nv_bfloat16 hi = __float2bfloat16(v);
        float lo = v - __bfloat162float(hi);
        size_t base = ((size_t)(k * COUT + co)) * 1024 + ci;
        g_wcat[base]       = hi;
        g_wcat[base + 512] = __float2bfloat16(lo);
    }
}

// ---------------------------------------------------------------------------
// Kernel 4: x -> modulated padded NHWC bf16 hi/lo split
// ---------------------------------------------------------------------------
__global__ void k_prepx(const float* __restrict__ x) {
    int h = blockIdx.x, b = blockIdx.y;
    int tid = threadIdx.x;
    __shared__ float t[32][65];
    __shared__ float sv[32];
    for (int chunk = 0; chunk < 16; chunk++) {
        int ci0 = chunk * 32;
        __syncthreads();
        {
            int r  = tid >> 5;
            int w2 = tid & 31;
#pragma unroll
            for (int rr = 0; rr < 4; rr++) {
                int cl = r * 4 + rr;
                const float* xp = x + (((size_t)b * CIN + ci0 + cl) * HH + h) * WW;
                t[cl][w2]      = xp[w2];
                t[cl][w2 + 32] = xp[w2 + 32];
            }
            if (tid < 32) sv[tid] = g_s[b * CIN + ci0 + tid];
        }
        __syncthreads();
        int ci = tid & 31, wg = tid >> 5;
        float s = sv[ci];
#pragma unroll
        for (int ww = 0; ww < 8; ww++) {
            int w = wg * 8 + ww;
            float v = t[ci][w] * s;
            __nv_bfloat16 hi = __float2bfloat16(v);
            float lo = v - __bfloat162float(hi);
            size_t base = (((size_t)b * 66 + h + 1) * 66 + (w + 1)) * 1024 + ci0 + ci;
            g_xcat[base]       = hi;
            g_xcat[base + 512] = __float2bfloat16(lo);
        }
    }
}

// ---------------------------------------------------------------------------
// Kernel 5: HMMA conv with shifted-window smem reuse.
// GEMM per CTA: M=co(128), N=spatial(128 = 2h x 64w).
// Stage = (pass, ci-chunk32): 48 stages.  Per stage smem:
//   A: 9 offsets x 128co x 32ci  (rows padded to 80B, conflict-free ldmatrix)
//   B: x patch 4x66 positions x 32ci (80B rows) -- all 9 offsets read shifted
//      windows of this one patch via per-lane ldmatrix addresses.
// 2-slot ring (113280 B/stage).  8 warps (4 co x 2 h), warp tile 32co x 64sp.
// ---------------------------------------------------------------------------
#define NSTG    48
#define A_BYTES (9 * 128 * 80)          /* 92160 */
#define P_BYTES (4 * 66 * 80)           /* 21120 */
#define STAGE   (A_BYTES + P_BYTES)     /* 113280 */
#define SMEM_SZ (2 * STAGE)             /* 226560 */

__global__ __launch_bounds__(256, 1) void k_conv_mma(float* __restrict__ out) {
    extern __shared__ char smem[];
    uint32_t sb = smem_u32(smem);

    int tid  = threadIdx.x;
    int lane = tid & 31;
    int warp = tid >> 5;
    int wm   = warp & 3;          // 0..3 -> co
    int wn   = warp >> 2;         // 0..1 -> output h row within tile
    int mBase = wm * 32;
    int nBase = wn * 64;

    int h0  = blockIdx.x * 2;     // 2 output h rows per CTA
    int P0  = blockIdx.x * 128;   // global spatial base
    int co0 = blockIdx.y * 128;
    int b   = blockIdx.z;

    const char* xb = (const char*)g_xcat;
    const char* wb = (const char*)g_wcat;

    float acc[2][8][4];
#pragma unroll
    for (int i = 0; i < 2; i++)
#pragma unroll
        for (int j = 0; j < 8; j++)
#pragma unroll
            for (int k = 0; k < 4; k++) acc[i][j][k] = 0.f;

    // ---- stage loader: stage -> (pass, ci chunk) ----
    auto load_stage = [&](int st) {
        int t  = st / 16;           // split pass: 0 hi*whi, 1 lo*whi, 2 hi*wlo
        int cc = st & 15;           // ci chunk of 32
        int wcol = ((t == 2) ? 512 : 0) + cc * 32;
        int xcol = ((t == 1) ? 512 : 0) + cc * 32;
        uint32_t As = sb + (st & 1) * STAGE;
        uint32_t Bp = As + A_BYTES;
        // A: 9 offsets x 128 rows x 64B
        for (int i = tid; i < 9 * 128 * 4; i += 256) {
            int o  = i >> 9;             // i / 512
            int rr = (i >> 2) & 127;
            int c  = i & 3;
            size_t off = (((size_t)o * COUT + co0 + rr) * 1024 + wcol) * 2 + (size_t)c * 16;
            cpa16(As + o * (128 * 80) + rr * 80 + c * 16, wb + off);
        }
        // B patch: 4 x 66 positions x 64B  (padded rows h0..h0+3, cols 0..65)
        for (int i = tid; i < 4 * 66 * 4; i += 256) {
            int pi = i >> 2;             // 0..263
            int c  = i & 3;
            int ph = pi / 66, pw = pi - ph * 66;
            size_t off = ((((size_t)b * 66 + h0 + ph) * 66 + pw) * 1024 + xcol) * 2 + (size_t)c * 16;
            cpa16(Bp + pi * 80 + c * 16, xb + off);
        }
        CP_COMMIT();
    };

    load_stage(0);
    load_stage(1);

    // per-thread ldmatrix lane addressing (row stride 80B)
    int aRow  = mBase + (lane & 15);                 // + mt*16
    int aKof  = (lane >> 4) * 16;                    // + ks*32
    int nLane = (lane & 7) + ((lane >> 4) << 3);     // row within 16-group
    int bk16  = ((lane >> 3) & 1) * 16;              // + ks*32

    for (int st = 0; st < NSTG; st++) {
        if (st == NSTG - 1) cp_wait<0>(); else cp_wait<1>();
        __syncthreads();
        uint32_t As = sb + (st & 1) * STAGE;
        uint32_t Bp = As + A_BYTES;

#pragma unroll
        for (int ky = 0; ky < 3; ky++) {
#pragma unroll
            for (int kx = 0; kx < 3; kx++) {
                uint32_t Ao = As + (ky * 3 + kx) * (128 * 80);
                // patch position base for this warp's 64-wide row
                uint32_t Bo = Bp + ((wn + ky) * 66 + kx) * 80;
#pragma unroll
                for (int ks = 0; ks < 2; ks++) {
                    uint32_t a[2][4];
#pragma unroll
                    for (int mt = 0; mt < 2; mt++)
                        ldsm4(a[mt], Ao + (aRow + mt * 16) * 80 + aKof + ks * 32);
                    uint32_t bf[4][4];
#pragma unroll
                    for (int ng = 0; ng < 4; ng++)
                        ldsm4(bf[ng], Bo + (nLane + ng * 16) * 80 + bk16 + ks * 32);
#pragma unroll
                    for (int mt = 0; mt < 2; mt++)
#pragma unroll
                        for (int ng = 0; ng < 4; ng++) {
                            mma16816(acc[mt][ng * 2 + 0], a[mt], bf[ng][0], bf[ng][1]);
                            mma16816(acc[mt][ng * 2 + 1], a[mt], bf[ng][2], bf[ng][3]);
                        }
                }
            }
        }

        __syncthreads();
        if (st + 2 < NSTG) load_stage(st + 2);
    }

    // ---- epilogue: demod scale + float2 stores (w-contiguous) ----
#pragma unroll
    for (int mt = 0; mt < 2; mt++) {
#pragma unroll
        for (int r = 0; r < 2; r++) {
            int co = co0 + mBase + mt * 16 + (lane >> 2) + r * 8;
            float dm = g_demod[b * COUT + co];
            float* op = out + (((size_t)b * COUT + co) << 12);
#pragma unroll
            for (int j = 0; j < 8; j++) {
                int n = nBase + (j >> 1) * 16 + (j & 1) * 8 + 2 * (lane & 3);
                float2 v;
                v.x = acc[mt][j][r * 2 + 0] * dm;
                v.y = acc[mt][j][r * 2 + 1] * dm;
                *(float2*)(op + P0 + n) = v;
            }
        }
    }
}

// ---------------------------------------------------------------------------
extern "C" void kernel_launch(void* const* d_in, const int* in_sizes, int n_in,
                              void* d_out, int out_size) {
    const float* x      = (const float*)d_in[0];  // [16,512,64,64]
    const float* style  = (const float*)d_in[1];  // [16,512]
    const float* weight = (const float*)d_in[2];  // [1,512,512,3,3]
    const float* mw     = (const float*)d_in[3];  // [512,512]
    const float* mb     = (const float*)d_in[4];  // [512]
    float* out          = (float*)d_out;          // [16,512,64,64]

    k_style<<<BB, SDIM>>>(style, mw, mb);
    k_prepw<<<COUT, CIN>>>(weight);
    k_demod<<<COUT, 256>>>(weight);
    {
        dim3 g(HH, BB);
        k_prepx<<<g, 256>>>(x);
    }
    cudaFuncSetAttribute(k_conv_mma, cudaFuncAttributeMaxDynamicSharedMemorySize, SMEM_SZ);
    {
        dim3 g(32 /*spatial tiles*/, 4 /*co tiles*/, BB);
        k_conv_mma<<<g, 256, SMEM_SZ>>>(out);
    }
}

// round 8
// speedup vs baseline: 5.1177x; 1.0840x over previous
#include <cuda_runtime.h>
#include <cuda_bf16.h>
#include <cstdint>

#define BB   16
#define CIN  512
#define COUT 512
#define HH   64
#define WW   64
#define SDIM 512

#define CONV_SCALE 0.014731391274719737f   /* 1/sqrt(512*9) */
#define MOD_SCALE  0.04419417382415922f    /* 1/sqrt(512)   */
#define EPS        1e-8f

// ---------------------------------------------------------------------------
// Device scratch (allocation-free rule: __device__ globals, zero-initialized)
// ---------------------------------------------------------------------------
__device__ float g_s[BB * CIN];                 // modulation scales s[b][ci]
__device__ float g_demod[BB * COUT];            // demod[b][co]
// Padded NHWC modulated input, bf16 split: [b][66][66][hi:512 | lo:512]
// Borders (row/col 0 and 65) never written -> stay zero (static zero-init).
__device__ __nv_bfloat16 g_xcat[(size_t)BB * 66 * 66 * 1024];
// Weights, bf16 split: [k(9)][co(512)][hi:512 | lo:512], pre-scaled by CONV_SCALE
__device__ __nv_bfloat16 g_wcat[(size_t)9 * COUT * 1024];

// ---------------------------------------------------------------------------
// PTX helpers (base ISA only: cp.async / ldmatrix / mma.sync)
// ---------------------------------------------------------------------------
__device__ __forceinline__ uint32_t smem_u32(const void* p) {
    uint32_t a;
    asm("{ .reg .u64 t; cvta.to.shared.u64 t, %1; cvt.u32.u64 %0, t; }" : "=r"(a) : "l"(p));
    return a;
}
__device__ __forceinline__ void cpa16(uint32_t dst, const void* src) {
    asm volatile("cp.async.cg.shared.global [%0], [%1], 16;" :: "r"(dst), "l"(src));
}
#define CP_COMMIT() asm volatile("cp.async.commit_group;" ::: "memory")
template <int N>
__device__ __forceinline__ void cp_wait() {
    asm volatile("cp.async.wait_group %0;" :: "n"(N) : "memory");
}
__device__ __forceinline__ void ldsm4(uint32_t* r, uint32_t addr) {
    asm volatile("ldmatrix.sync.aligned.m8n8.x4.shared.b16 {%0,%1,%2,%3}, [%4];"
                 : "=r"(r[0]), "=r"(r[1]), "=r"(r[2]), "=r"(r[3]) : "r"(addr));
}
__device__ __forceinline__ void mma16816(float* d, const uint32_t* a,
                                         uint32_t b0, uint32_t b1) {
    asm volatile(
        "mma.sync.aligned.m16n8k16.row.col.f32.bf16.bf16.f32 "
        "{%0,%1,%2,%3}, {%4,%5,%6,%7}, {%8,%9}, {%0,%1,%2,%3};"
        : "+f"(d[0]), "+f"(d[1]), "+f"(d[2]), "+f"(d[3])
        : "r"(a[0]), "r"(a[1]), "r"(a[2]), "r"(a[3]), "r"(b0), "r"(b1));
}

// ---------------------------------------------------------------------------
// Kernel 1: s[b][ci] = style[b] . (mod_weight[ci] * MOD_SCALE) + mod_bias[ci]
// ---------------------------------------------------------------------------
__global__ void k_style(const float* __restrict__ style,
                        const float* __restrict__ mw,
                        const float* __restrict__ mb) {
    __shared__ float st[SDIM];
    int b = blockIdx.x;
    int t = threadIdx.x;
    st[t] = style[b * SDIM + t];
    __syncthreads();
    const float4* wrow = (const float4*)(mw + (size_t)t * SDIM);
    const float4* srow = (const float4*)st;
    float acc = 0.f;
#pragma unroll 8
    for (int j = 0; j < SDIM / 4; j++) {
        float4 w4 = wrow[j];
        float4 s4 = srow[j];
        acc += w4.x * s4.x + w4.y * s4.y + w4.z * s4.z + w4.w * s4.w;
    }
    g_s[b * CIN + t] = acc * MOD_SCALE + mb[t];
}

// ---------------------------------------------------------------------------
// Kernel 2: demod[b][co]
// ---------------------------------------------------------------------------
__global__ void k_demod(const float* __restrict__ w) {
    int co = blockIdx.x;
    int t  = threadIdx.x;
    float acc[BB];
#pragma unroll
    for (int b = 0; b < BB; b++) acc[b] = 0.f;

    for (int ci = t; ci < CIN; ci += 256) {
        const float* wp = w + ((size_t)co * CIN + ci) * 9;
        float wsq = 0.f;
#pragma unroll
        for (int i = 0; i < 9; i++) wsq += wp[i] * wp[i];
#pragma unroll
        for (int b = 0; b < BB; b++) {
            float sv = g_s[b * CIN + ci];
            acc[b] += wsq * sv * sv;
        }
    }

    __shared__ float red[BB][257];
#pragma unroll
    for (int b = 0; b < BB; b++) red[b][t] = acc[b];
    __syncthreads();
    for (int off = 128; off > 0; off >>= 1) {
        if (t < off) {
#pragma unroll
            for (int b = 0; b < BB; b++) red[b][t] += red[b][t + off];
        }
        __syncthreads();
    }
    if (t < BB) {
        float v = red[t][0];
        g_demod[t * COUT + co] = rsqrtf(CONV_SCALE * CONV_SCALE * v + EPS);
    }
}

// ---------------------------------------------------------------------------
// Kernel 3: weights -> bf16 hi/lo split, [k][co][hi|lo], pre-scaled
// ---------------------------------------------------------------------------
__global__ void k_prepw(const float* __restrict__ wt) {
    int co = blockIdx.x, ci = threadIdx.x;
    const float* wp = wt + ((size_t)co * CIN + ci) * 9;
#pragma unroll
    for (int k = 0; k < 9; k++) {
        float v = CONV_SCALE * wp[k];
        __nv_bfloat16 hi = __float2bfloat16(v);
        float lo = v - __bfloat162float(hi);
        size_t base = ((size_t)(k * COUT + co)) * 1024 + ci;
        g_wcat[base]       = hi;
        g_wcat[base + 512] = __float2bfloat16(lo);
    }
}

// ---------------------------------------------------------------------------
// Kernel 4: x -> modulated padded NHWC bf16 hi/lo split
// ---------------------------------------------------------------------------
__global__ void k_prepx(const float* __restrict__ x) {
    int h = blockIdx.x, b = blockIdx.y;
    int tid = threadIdx.x;
    __shared__ float t[32][65];
    __shared__ float sv[32];
    for (int chunk = 0; chunk < 16; chunk++) {
        int ci0 = chunk * 32;
        __syncthreads();
        {
            int r  = tid >> 5;
            int w2 = tid & 31;
#pragma unroll
            for (int rr = 0; rr < 4; rr++) {
                int cl = r * 4 + rr;
                const float* xp = x + (((size_t)b * CIN + ci0 + cl) * HH + h) * WW;
                t[cl][w2]      = xp[w2];
                t[cl][w2 + 32] = xp[w2 + 32];
            }
            if (tid < 32) sv[tid] = g_s[b * CIN + ci0 + tid];
        }
        __syncthreads();
        int ci = tid & 31, wg = tid >> 5;
        float s = sv[ci];
#pragma unroll
        for (int ww = 0; ww < 8; ww++) {
            int w = wg * 8 + ww;
            float v = t[ci][w] * s;
            __nv_bfloat16 hi = __float2bfloat16(v);
            float lo = v - __bfloat162float(hi);
            size_t base = (((size_t)b * 66 + h + 1) * 66 + (w + 1)) * 1024 + ci0 + ci;
            g_xcat[base]       = hi;
            g_xcat[base + 512] = __float2bfloat16(lo);
        }
    }
}

// ---------------------------------------------------------------------------
// Kernel 5: HMMA conv, shifted-window reuse + A-tile reuse across passes.
// Stage order: st<32: (cc=st>>1, t=st&1) -- t0/t1 PAIR SHARES the whi A tile;
//              st>=32: (cc=st-32, t=2)  -- wlo A tiles.
// A ring: 2 slots, advances only on A loads (32 per CTA, was 48).
// B ring: 2 slots, every stage.  Fixed 2 commit groups per stage
// (GA may be empty) => exact cp.async.wait_group accounting.
// A prefetch for st+2 issues BEFORE compute when slot-safe (st<=30).
// ---------------------------------------------------------------------------
#define NSTG    48
#define A_BYTES (9 * 128 * 80)          /* 92160 per A slot */
#define P_BYTES (4 * 66 * 80)           /* 21120 per B slot */
#define SMEM_SZ (2 * A_BYTES + 2 * P_BYTES)   /* 226560 */

// stage -> t (pass)
__device__ __forceinline__ int stg_t(int st)  { return (st < 32) ? (st & 1) : 2; }
// stage -> ci chunk
__device__ __forceinline__ int stg_cc(int st) { return (st < 32) ? (st >> 1) : (st - 32); }
// stage -> A-load index (monotone; equal for t0/t1 pairs)
__device__ __forceinline__ int stg_ai(int st) { return (st < 32) ? (st >> 1) : (st - 16); }

__global__ __launch_bounds__(256, 1) void k_conv_mma(float* __restrict__ out) {
    extern __shared__ char smem[];
    uint32_t sb = smem_u32(smem);
    uint32_t Bbase = sb + 2 * A_BYTES;

    int tid  = threadIdx.x;
    int lane = tid & 31;
    int warp = tid >> 5;
    int wm   = warp & 3;          // 0..3 -> co
    int wn   = warp >> 2;         // 0..1 -> output h row within tile
    int mBase = wm * 32;
    int nBase = wn * 64;

    int h0  = blockIdx.x * 2;     // 2 output h rows per CTA
    int P0  = blockIdx.x * 128;   // global spatial base
    int co0 = blockIdx.y * 128;
    int b   = blockIdx.z;

    const char* xb = (const char*)g_xcat;
    const char* wb = (const char*)g_wcat;

    float acc[2][8][4];
#pragma unroll
    for (int i = 0; i < 2; i++)
#pragma unroll
        for (int j = 0; j < 8; j++)
#pragma unroll
            for (int k = 0; k < 4; k++) acc[i][j][k] = 0.f;

    // ---- A loader: weights for stage st (skipped => empty commit group) ----
    auto load_A = [&](int st) {
        int t = stg_t(st);
        if (t != 1) {
            int cc   = stg_cc(st);
            int wcol = ((t == 2) ? 512 : 0) + cc * 32;
            uint32_t As = sb + (stg_ai(st) & 1) * A_BYTES;
            for (int i = tid; i < 9 * 128 * 4; i += 256) {
                int o  = i >> 9;
                int rr = (i >> 2) & 127;
                int c  = i & 3;
                size_t off = (((size_t)o * COUT + co0 + rr) * 1024 + wcol) * 2 + (size_t)c * 16;
                cpa16(As + o * (128 * 80) + rr * 80 + c * 16, wb + off);
            }
        }
        CP_COMMIT();
    };
    // ---- B loader: x patch for stage st ----
    auto load_B = [&](int st) {
        int t    = stg_t(st);
        int cc   = stg_cc(st);
        int xcol = ((t == 1) ? 512 : 0) + cc * 32;
        uint32_t Bp = Bbase + (st & 1) * P_BYTES;
        for (int i = tid; i < 4 * 66 * 4; i += 256) {
            int pi = i >> 2;
            int c  = i & 3;
            int ph = pi / 66, pw = pi - ph * 66;
            size_t off = ((((size_t)b * 66 + h0 + ph) * 66 + pw) * 1024 + xcol) * 2 + (size_t)c * 16;
            cpa16(Bp + pi * 80 + c * 16, xb + off);
        }
        CP_COMMIT();
    };

    load_A(0); load_B(0);
    load_A(1); load_B(1);   // A(1) is t1 -> empty group (count stays fixed)

    // per-thread ldmatrix lane addressing (row stride 80B)
    int aRow  = mBase + (lane & 15);
    int aKof  = (lane >> 4) * 16;
    int nLane = (lane & 7) + ((lane >> 4) << 3);
    int bk16  = ((lane >> 3) & 1) * 16;

    for (int st = 0; st < NSTG; st++) {
        if (st == NSTG - 1) cp_wait<0>(); else cp_wait<2>();
        __syncthreads();

        // Early A prefetch for st+2 (safe while A ring rotates at half rate:
        // write slot != slots read by stages st, st+1 for all st <= 30).
        bool early = (st + 2 < NSTG) && (st <= 30);
        if (early) load_A(st + 2);

        uint32_t As = sb + (stg_ai(st) & 1) * A_BYTES;
        uint32_t Bp = Bbase + (st & 1) * P_BYTES;

#pragma unroll
        for (int ky = 0; ky < 3; ky++) {
#pragma unroll
            for (int kx = 0; kx < 3; kx++) {
                uint32_t Ao = As + (ky * 3 + kx) * (128 * 80);
                uint32_t Bo = Bp + ((wn + ky) * 66 + kx) * 80;
#pragma unroll
                for (int ks = 0; ks < 2; ks++) {
                    uint32_t a[2][4];
#pragma unroll
                    for (int mt = 0; mt < 2; mt++)
                        ldsm4(a[mt], Ao + (aRow + mt * 16) * 80 + aKof + ks * 32);
                    uint32_t bf[4][4];
#pragma unroll
                    for (int ng = 0; ng < 4; ng++)
                        ldsm4(bf[ng], Bo + (nLane + ng * 16) * 80 + bk16 + ks * 32);
#pragma unroll
                    for (int mt = 0; mt < 2; mt++)
#pragma unroll
                        for (int ng = 0; ng < 4; ng++) {
                            mma16816(acc[mt][ng * 2 + 0], a[mt], bf[ng][0], bf[ng][1]);
                            mma16816(acc[mt][ng * 2 + 1], a[mt], bf[ng][2], bf[ng][3]);
                        }
                }
            }
        }

        __syncthreads();
        if (st + 2 < NSTG) {
            if (!early) load_A(st + 2);   // t2 region: slot written == slot just read
            load_B(st + 2);
        }
    }

    // ---- epilogue: demod scale + float2 stores (w-contiguous) ----
#pragma unroll
    for (int mt = 0; mt < 2; mt++) {
#pragma unroll
        for (int r = 0; r < 2; r++) {
            int co = co0 + mBase + mt * 16 + (lane >> 2) + r * 8;
            float dm = g_demod[b * COUT + co];
            float* op = out + (((size_t)b * COUT + co) << 12);
#pragma unroll
            for (int j = 0; j < 8; j++) {
                int n = nBase + (j >> 1) * 16 + (j & 1) * 8 + 2 * (lane & 3);
                float2 v;
                v.x = acc[mt][j][r * 2 + 0] * dm;
                v.y = acc[mt][j][r * 2 + 1] * dm;
                *(float2*)(op + P0 + n) = v;
            }
        }
    }
}

// ---------------------------------------------------------------------------
extern "C" void kernel_launch(void* const* d_in, const int* in_sizes, int n_in,
                              void* d_out, int out_size) {
    const float* x      = (const float*)d_in[0];  // [16,512,64,64]
    const float* style  = (const float*)d_in[1];  // [16,512]
    const float* weight = (const float*)d_in[2];  // [1,512,512,3,3]
    const float* mw     = (const float*)d_in[3];  // [512,512]
    const float* mb     = (const float*)d_in[4];  // [512]
    float* out          = (float*)d_out;          // [16,512,64,64]

    k_style<<<BB, SDIM>>>(style, mw, mb);
    k_prepw<<<COUT, CIN>>>(weight);
    k_demod<<<COUT, 256>>>(weight);
    {
        dim3 g(HH, BB);
        k_prepx<<<g, 256>>>(x);
    }
    cudaFuncSetAttribute(k_conv_mma, cudaFuncAttributeMaxDynamicSharedMemorySize, SMEM_SZ);
    {
        dim3 g(32 /*spatial tiles*/, 4 /*co tiles*/, BB);
        k_conv_mma<<<g, 256, SMEM_SZ>>>(out);
    }
}

// round 10
// speedup vs baseline: 6.2122x; 1.2139x over previous
#include <cuda_runtime.h>
#include <cuda_bf16.h>
#include <cstdint>

#define BB   16
#define CIN  512
#define COUT 512
#define HH   64
#define WW   64
#define SDIM 512

#define CONV_SCALE 0.014731391274719737f   /* 1/sqrt(512*9) */
#define MOD_SCALE  0.04419417382415922f    /* 1/sqrt(512)   */
#define EPS        1e-8f

// ---------------------------------------------------------------------------
// Device scratch (allocation-free rule: __device__ globals, zero-initialized)
// ---------------------------------------------------------------------------
__device__ float g_s[BB * CIN];
__device__ float g_demod[BB * COUT];
// Padded NHWC modulated input, bf16 split: [b][66][66][hi:512 | lo:512]
__device__ __nv_bfloat16 g_xcat[(size_t)BB * 66 * 66 * 1024];
// Weights, bf16 split: [k(9)][co(512)][hi:512 | lo:512], pre-scaled
__device__ __nv_bfloat16 g_wcat[(size_t)9 * COUT * 1024];

// ---------------------------------------------------------------------------
// PTX helpers (base ISA only)
// ---------------------------------------------------------------------------
__device__ __forceinline__ uint32_t smem_u32(const void* p) {
    uint32_t a;
    asm("{ .reg .u64 t; cvta.to.shared.u64 t, %1; cvt.u32.u64 %0, t; }" : "=r"(a) : "l"(p));
    return a;
}
__device__ __forceinline__ void cpa16(uint32_t dst, const void* src) {
    asm volatile("cp.async.cg.shared.global [%0], [%1], 16;" :: "r"(dst), "l"(src));
}
#define CP_COMMIT() asm volatile("cp.async.commit_group;" ::: "memory")
template <int N>
__device__ __forceinline__ void cp_wait() {
    asm volatile("cp.async.wait_group %0;" :: "n"(N) : "memory");
}
__device__ __forceinline__ void ldsm4(uint32_t* r, uint32_t addr) {
    asm volatile("ldmatrix.sync.aligned.m8n8.x4.shared.b16 {%0,%1,%2,%3}, [%4];"
                 : "=r"(r[0]), "=r"(r[1]), "=r"(r[2]), "=r"(r[3]) : "r"(addr));
}
__device__ __forceinline__ void mma16816(float* d, const uint32_t* a,
                                         uint32_t b0, uint32_t b1) {
    asm volatile(
        "mma.sync.aligned.m16n8k16.row.col.f32.bf16.bf16.f32 "
        "{%0,%1,%2,%3}, {%4,%5,%6,%7}, {%8,%9}, {%0,%1,%2,%3};"
        : "+f"(d[0]), "+f"(d[1]), "+f"(d[2]), "+f"(d[3])
        : "r"(a[0]), "r"(a[1]), "r"(a[2]), "r"(a[3]), "r"(b0), "r"(b1));
}
// 64B-row swizzle: phys = row*64 + ((chunk ^ ((row>>1)&3))<<4)
__device__ __forceinline__ uint32_t sw64(int row, int chunk) {
    return (uint32_t)(row * 64 + (((chunk ^ ((row >> 1) & 3)) & 3) << 4));
}

// ---------------------------------------------------------------------------
// Kernel 1: modulation scales
// ---------------------------------------------------------------------------
__global__ void k_style(const float* __restrict__ style,
                        const float* __restrict__ mw,
                        const float* __restrict__ mb) {
    __shared__ float st[SDIM];
    int b = blockIdx.x;
    int t = threadIdx.x;
    st[t] = style[b * SDIM + t];
    __syncthreads();
    const float4* wrow = (const float4*)(mw + (size_t)t * SDIM);
    const float4* srow = (const float4*)st;
    float acc = 0.f;
#pragma unroll 8
    for (int j = 0; j < SDIM / 4; j++) {
        float4 w4 = wrow[j];
        float4 s4 = srow[j];
        acc += w4.x * s4.x + w4.y * s4.y + w4.z * s4.z + w4.w * s4.w;
    }
    g_s[b * CIN + t] = acc * MOD_SCALE + mb[t];
}

// ---------------------------------------------------------------------------
// Kernel 2: demod[b][co]
// ---------------------------------------------------------------------------
__global__ void k_demod(const float* __restrict__ w) {
    int co = blockIdx.x;
    int t  = threadIdx.x;
    float acc[BB];
#pragma unroll
    for (int b = 0; b < BB; b++) acc[b] = 0.f;

    for (int ci = t; ci < CIN; ci += 256) {
        const float* wp = w + ((size_t)co * CIN + ci) * 9;
        float wsq = 0.f;
#pragma unroll
        for (int i = 0; i < 9; i++) wsq += wp[i] * wp[i];
#pragma unroll
        for (int b = 0; b < BB; b++) {
            float sv = g_s[b * CIN + ci];
            acc[b] += wsq * sv * sv;
        }
    }

    __shared__ float red[BB][257];
#pragma unroll
    for (int b = 0; b < BB; b++) red[b][t] = acc[b];
    __syncthreads();
    for (int off = 128; off > 0; off >>= 1) {
        if (t < off) {
#pragma unroll
            for (int b = 0; b < BB; b++) red[b][t] += red[b][t + off];
        }
        __syncthreads();
    }
    if (t < BB) {
        float v = red[t][0];
        g_demod[t * COUT + co] = rsqrtf(CONV_SCALE * CONV_SCALE * v + EPS);
    }
}

// ---------------------------------------------------------------------------
// Kernel 3: weights -> bf16 hi/lo split
// ---------------------------------------------------------------------------
__global__ void k_prepw(const float* __restrict__ wt) {
    int co = blockIdx.x, ci = threadIdx.x;
    const float* wp = wt + ((size_t)co * CIN + ci) * 9;
#pragma unroll
    for (int k = 0; k < 9; k++) {
        float v = CONV_SCALE * wp[k];
        __nv_bfloat16 hi = __float2bfloat16(v);
        float lo = v - __bfloat162float(hi);
        size_t base = ((size_t)(k * COUT + co)) * 1024 + ci;
        g_wcat[base]       = hi;
        g_wcat[base + 512] = __float2bfloat16(lo);
    }
}

// ---------------------------------------------------------------------------
// Kernel 4: x -> modulated padded NHWC bf16 hi/lo split
// ---------------------------------------------------------------------------
__global__ void k_prepx(const float* __restrict__ x) {
    int h = blockIdx.x, b = blockIdx.y;
    int tid = threadIdx.x;
    __shared__ float t[32][65];
    __shared__ float sv[32];
    for (int chunk = 0; chunk < 16; chunk++) {
        int ci0 = chunk * 32;
        __syncthreads();
        {
            int r  = tid >> 5;
            int w2 = tid & 31;
#pragma unroll
            for (int rr = 0; rr < 4; rr++) {
                int cl = r * 4 + rr;
                const float* xp = x + (((size_t)b * CIN + ci0 + cl) * HH + h) * WW;
                t[cl][w2]      = xp[w2];
                t[cl][w2 + 32] = xp[w2 + 32];
            }
            if (tid < 32) sv[tid] = g_s[b * CIN + ci0 + tid];
        }
        __syncthreads();
        int ci = tid & 31, wg = tid >> 5;
        float s = sv[ci];
#pragma unroll
        for (int ww = 0; ww < 8; ww++) {
            int w = wg * 8 + ww;
            float v = t[ci][w] * s;
            __nv_bfloat16 hi = __float2bfloat16(v);
            float lo = v - __bfloat162float(hi);
            size_t base = (((size_t)b * 66 + h + 1) * 66 + (w + 1)) * 1024 + ci0 + ci;
            g_xcat[base]       = hi;
            g_xcat[base + 512] = __float2bfloat16(lo);
        }
    }
}

// ---------------------------------------------------------------------------
// Kernel 5: HMMA conv.  Per CTA: M=co(128), N=spatial(256 = 4h x 64w).
// 8 warps (4 co x 2 h-pairs), warp tile 32co x 128sp (2 h rows).
// Smem: swizzled 64B rows.  A: 9 offs x 128co x 32ci (73728B/slot);
// B: 6x66 patch x 32ci (25344B/slot); 2 slots each = 198144B.
// Stage order (48): st<32: (cc=st>>1, t=st&1) share whi A; st>=32: t=2.
// ---------------------------------------------------------------------------
#define NSTG    48
#define A_BYTES (9 * 128 * 64)          /* 73728 per A slot */
#define P_BYTES (6 * 66 * 64)           /* 25344 per B slot */
#define SMEM_SZ (2 * A_BYTES + 2 * P_BYTES)   /* 198144 */

__device__ __forceinline__ int stg_t(int st)  { return (st < 32) ? (st & 1) : 2; }
__device__ __forceinline__ int stg_cc(int st) { return (st < 32) ? (st >> 1) : (st - 32); }
__device__ __forceinline__ int stg_ai(int st) { return (st < 32) ? (st >> 1) : (st - 16); }

__global__ __launch_bounds__(256, 1) void k_conv_mma(float* __restrict__ out) {
    extern __shared__ char smem[];
    uint32_t sb = smem_u32(smem);
    uint32_t Bbase = sb + 2 * A_BYTES;

    int tid  = threadIdx.x;
    int lane = tid & 31;
    int warp = tid >> 5;
    int wm   = warp & 3;          // 0..3 -> co
    int wn   = warp >> 2;         // 0..1 -> h-row pair (rows 2wn, 2wn+1)
    int mBase = wm * 32;

    int h0  = blockIdx.x * 4;     // 4 output h rows per CTA
    int co0 = blockIdx.y * 128;
    int b   = blockIdx.z;

    const char* xb = (const char*)g_xcat;
    const char* wb = (const char*)g_wcat;

    float acc[2][16][4];          // [mt][hr*8 + ng*2 + halfN][frag]
#pragma unroll
    for (int i = 0; i < 2; i++)
#pragma unroll
        for (int j = 0; j < 16; j++)
#pragma unroll
            for (int k = 0; k < 4; k++) acc[i][j][k] = 0.f;

    // ---- A loader (skipped for t1 => empty commit group) ----
    auto load_A = [&](int st) {
        int t = stg_t(st);
        if (t != 1) {
            int cc   = stg_cc(st);
            int wcol = ((t == 2) ? 512 : 0) + cc * 32;
            uint32_t As = sb + (stg_ai(st) & 1) * A_BYTES;
#pragma unroll
            for (int i = tid; i < 9 * 128 * 4; i += 256) {
                int o  = i >> 9;
                int rr = (i >> 2) & 127;
                int c  = i & 3;
                size_t off = (((size_t)o * COUT + co0 + rr) * 1024 + wcol) * 2 + (size_t)c * 16;
                cpa16(As + o * 8192 + sw64(rr, c), wb + off);
            }
        }
        CP_COMMIT();
    };
    // ---- B loader: 6x66 patch ----
    auto load_B = [&](int st) {
        int t    = stg_t(st);
        int cc   = stg_cc(st);
        int xcol = ((t == 1) ? 512 : 0) + cc * 32;
        uint32_t Bp = Bbase + (st & 1) * P_BYTES;
        for (int i = tid; i < 6 * 66 * 4; i += 256) {
            int pi = i >> 2;
            int c  = i & 3;
            int ph = pi / 66, pw = pi - ph * 66;
            size_t off = ((((size_t)b * 66 + h0 + ph) * 66 + pw) * 1024 + xcol) * 2 + (size_t)c * 16;
            cpa16(Bp + sw64(pi, c), xb + off);
        }
        CP_COMMIT();
    };

    load_A(0); load_B(0);
    load_A(1); load_B(1);

    // per-lane fragment addressing
    int aR0  = mBase + (lane & 15);
    int aSel = (aR0 >> 1) & 3;
    int ac0  = lane >> 4;                        // 0..1
    uint32_t aOff0 = (uint32_t)(((ac0 ^ aSel) & 3) << 4);
    uint32_t aOff1 = (uint32_t)((((ac0 + 2) ^ aSel) & 3) << 4);
    int nLane = (lane & 7) + ((lane >> 4) << 3);
    int cb0   = (lane >> 3) & 1;

    for (int st = 0; st < NSTG; st++) {
        if (st == NSTG - 1) cp_wait<0>(); else cp_wait<2>();
        __syncthreads();

        bool early = (st + 2 < NSTG) && (st <= 30);
        if (early) load_A(st + 2);

        uint32_t As = sb + (stg_ai(st) & 1) * A_BYTES;
        uint32_t Bp = Bbase + (st & 1) * P_BYTES;

#pragma unroll
        for (int ky = 0; ky < 3; ky++) {
#pragma unroll
            for (int kx = 0; kx < 3; kx++) {
                uint32_t Ao = As + (ky * 3 + kx) * 8192;
#pragma unroll
                for (int ks = 0; ks < 2; ks++) {
                    uint32_t aOff = ks ? aOff1 : aOff0;
                    uint32_t a[2][4];
#pragma unroll
                    for (int mt = 0; mt < 2; mt++)
                        ldsm4(a[mt], Ao + (uint32_t)(aR0 + mt * 16) * 64 + aOff);
#pragma unroll
                    for (int hr = 0; hr < 2; hr++) {
                        int q0 = (2 * wn + hr + ky) * 66 + kx + nLane;
                        int bSel = (q0 >> 1) & 3;
                        uint32_t bOff = (uint32_t)((((cb0 + 2 * ks) ^ bSel) & 3) << 4);
                        uint32_t Bq = Bp + (uint32_t)q0 * 64 + bOff;
#pragma unroll
                        for (int ng = 0; ng < 4; ng++) {
                            uint32_t bf[4];
                            ldsm4(bf, Bq + (uint32_t)ng * 1024);
#pragma unroll
                            for (int mt = 0; mt < 2; mt++) {
                                mma16816(acc[mt][hr * 8 + ng * 2 + 0], a[mt], bf[0], bf[1]);
                                mma16816(acc[mt][hr * 8 + ng * 2 + 1], a[mt], bf[2], bf[3]);
                            }
                        }
                    }
                }
            }
        }

        __syncthreads();
        if (st + 2 < NSTG) {
            if (!early) load_A(st + 2);
            load_B(st + 2);
        }
    }

    // ---- epilogue: demod scale + float2 stores ----
#pragma unroll
    for (int mt = 0; mt < 2; mt++) {
#pragma unroll
        for (int r = 0; r < 2; r++) {
            int co = co0 + mBase + mt * 16 + (lane >> 2) + r * 8;
            float dm = g_demod[b * COUT + co];
            float* op = out + (((size_t)b * COUT + co) << 12);
#pragma unroll
            for (int hr = 0; hr < 2; hr++) {
                int h = h0 + 2 * wn + hr;
#pragma unroll
                for (int j = 0; j < 8; j++) {
                    int n = (j >> 1) * 16 + (j & 1) * 8 + 2 * (lane & 3);
                    float2 v;
                    v.x = acc[mt][hr * 8 + j][r * 2 + 0] * dm;
                    v.y = acc[mt][hr * 8 + j][r * 2 + 1] * dm;
                    *(float2*)(op + h * 64 + n) = v;
                }
            }
        }
    }
}

// ---------------------------------------------------------------------------
extern "C" void kernel_launch(void* const* d_in, const int* in_sizes, int n_in,
                              void* d_out, int out_size) {
    const float* x      = (const float*)d_in[0];  // [16,512,64,64]
    const float* style  = (const float*)d_in[1];  // [16,512]
    const float* weight = (const float*)d_in[2];  // [1,512,512,3,3]
    const float* mw     = (const float*)d_in[3];  // [512,512]
    const float* mb     = (const float*)d_in[4];  // [512]
    float* out          = (float*)d_out;          // [16,512,64,64]

    k_style<<<BB, SDIM>>>(style, mw, mb);
    k_prepw<<<COUT, CIN>>>(weight);
    k_demod<<<COUT, 256>>>(weight);
    {
        dim3 g(HH, BB);
        k_prepx<<<g, 256>>>(x);
    }
    cudaFuncSetAttribute(k_conv_mma, cudaFuncAttributeMaxDynamicSharedMemorySize, SMEM_SZ);
    {
        dim3 g(16 /*spatial tiles*/, 4 /*co tiles*/, BB);
        k_conv_mma<<<g, 256, SMEM_SZ>>>(out);
    }
}

// round 11
// speedup vs baseline: 8.4252x; 1.3562x over previous
#include <cuda_runtime.h>
#include <cuda_bf16.h>
#include <cstdint>

#define BB   16
#define CIN  512
#define COUT 512
#define HH   64
#define WW   64
#define SDIM 512

#define CONV_SCALE 0.014731391274719737f   /* 1/sqrt(512*9) */
#define MOD_SCALE  0.04419417382415922f    /* 1/sqrt(512)   */
#define EPS        1e-8f

// ---------------------------------------------------------------------------
// Device scratch (allocation-free rule: __device__ globals, zero-initialized)
// ---------------------------------------------------------------------------
__device__ float g_s[BB * CIN];
__device__ float g_demod[BB * COUT];
// Padded NHWC modulated input, tf32-rounded fp32: [b][66][66][ci:512]
// Borders (row/col 0 and 65) never written -> stay zero (static zero-init).
__device__ float g_xcat[(size_t)BB * 66 * 66 * 512];
// Weights tf32-rounded fp32: [k(9)][co(512)][ci(512)], pre-scaled by CONV_SCALE
__device__ float g_wcat[(size_t)9 * COUT * CIN];

// ---------------------------------------------------------------------------
// PTX helpers (base ISA only: cp.async / ldmatrix / mma.sync tf32)
// ---------------------------------------------------------------------------
__device__ __forceinline__ uint32_t smem_u32(const void* p) {
    uint32_t a;
    asm("{ .reg .u64 t; cvta.to.shared.u64 t, %1; cvt.u32.u64 %0, t; }" : "=r"(a) : "l"(p));
    return a;
}
__device__ __forceinline__ void cpa16(uint32_t dst, const void* src) {
    asm volatile("cp.async.cg.shared.global [%0], [%1], 16;" :: "r"(dst), "l"(src));
}
#define CP_COMMIT() asm volatile("cp.async.commit_group;" ::: "memory")
template <int N>
__device__ __forceinline__ void cp_wait() {
    asm volatile("cp.async.wait_group %0;" :: "n"(N) : "memory");
}
__device__ __forceinline__ void ldsm4(uint32_t* r, uint32_t addr) {
    asm volatile("ldmatrix.sync.aligned.m8n8.x4.shared.b16 {%0,%1,%2,%3}, [%4];"
                 : "=r"(r[0]), "=r"(r[1]), "=r"(r[2]), "=r"(r[3]) : "r"(addr));
}
// tf32 mma: D(16x8) += A(16x8) * B(8x8); A,B are 32-bit tf32 regs
__device__ __forceinline__ void mma1688(float* d, const uint32_t* a,
                                        uint32_t b0, uint32_t b1) {
    asm volatile(
        "mma.sync.aligned.m16n8k8.row.col.f32.tf32.tf32.f32 "
        "{%0,%1,%2,%3}, {%4,%5,%6,%7}, {%8,%9}, {%0,%1,%2,%3};"
        : "+f"(d[0]), "+f"(d[1]), "+f"(d[2]), "+f"(d[3])
        : "r"(a[0]), "r"(a[1]), "r"(a[2]), "r"(a[3]), "r"(b0), "r"(b1));
}
__device__ __forceinline__ float to_tf32(float v) {
    uint32_t r;
    asm("cvt.rna.tf32.f32 %0, %1;" : "=r"(r) : "f"(v));
    return __uint_as_float(r);
}

// ---------------------------------------------------------------------------
// Kernel 1: modulation scales
// ---------------------------------------------------------------------------
__global__ void k_style(const float* __restrict__ style,
                        const float* __restrict__ mw,
                        const float* __restrict__ mb) {
    __shared__ float st[SDIM];
    int b = blockIdx.x;
    int t = threadIdx.x;
    st[t] = style[b * SDIM + t];
    __syncthreads();
    const float4* wrow = (const float4*)(mw + (size_t)t * SDIM);
    const float4* srow = (const float4*)st;
    float acc = 0.f;
#pragma unroll 8
    for (int j = 0; j < SDIM / 4; j++) {
        float4 w4 = wrow[j];
        float4 s4 = srow[j];
        acc += w4.x * s4.x + w4.y * s4.y + w4.z * s4.z + w4.w * s4.w;
    }
    g_s[b * CIN + t] = acc * MOD_SCALE + mb[t];
}

// ---------------------------------------------------------------------------
// Kernel 2: demod[b][co]  (exact fp32 weights -- matches reference)
// ---------------------------------------------------------------------------
__global__ void k_demod(const float* __restrict__ w) {
    int co = blockIdx.x;
    int t  = threadIdx.x;
    float acc[BB];
#pragma unroll
    for (int b = 0; b < BB; b++) acc[b] = 0.f;

    for (int ci = t; ci < CIN; ci += 256) {
        const float* wp = w + ((size_t)co * CIN + ci) * 9;
        float wsq = 0.f;
#pragma unroll
        for (int i = 0; i < 9; i++) wsq += wp[i] * wp[i];
#pragma unroll
        for (int b = 0; b < BB; b++) {
            float sv = g_s[b * CIN + ci];
            acc[b] += wsq * sv * sv;
        }
    }

    __shared__ float red[BB][257];
#pragma unroll
    for (int b = 0; b < BB; b++) red[b][t] = acc[b];
    __syncthreads();
    for (int off = 128; off > 0; off >>= 1) {
        if (t < off) {
#pragma unroll
            for (int b = 0; b < BB; b++) red[b][t] += red[b][t + off];
        }
        __syncthreads();
    }
    if (t < BB) {
        float v = red[t][0];
        g_demod[t * COUT + co] = rsqrtf(CONV_SCALE * CONV_SCALE * v + EPS);
    }
}

// ---------------------------------------------------------------------------
// Kernel 3: weights -> tf32-rounded, [k][co][ci], pre-scaled
// ---------------------------------------------------------------------------
__global__ void k_prepw(const float* __restrict__ wt) {
    int co = blockIdx.x, ci = threadIdx.x;
    const float* wp = wt + ((size_t)co * CIN + ci) * 9;
#pragma unroll
    for (int k = 0; k < 9; k++) {
        g_wcat[((size_t)k * COUT + co) * CIN + ci] = to_tf32(CONV_SCALE * wp[k]);
    }
}

// ---------------------------------------------------------------------------
// Kernel 4: x -> modulated padded NHWC tf32-rounded
// ---------------------------------------------------------------------------
__global__ void k_prepx(const float* __restrict__ x) {
    int h = blockIdx.x, b = blockIdx.y;
    int tid = threadIdx.x;
    __shared__ float t[32][65];
    __shared__ float sv[32];
    for (int chunk = 0; chunk < 16; chunk++) {
        int ci0 = chunk * 32;
        __syncthreads();
        {
            int r  = tid >> 5;
            int w2 = tid & 31;
#pragma unroll
            for (int rr = 0; rr < 4; rr++) {
                int cl = r * 4 + rr;
                const float* xp = x + (((size_t)b * CIN + ci0 + cl) * HH + h) * WW;
                t[cl][w2]      = xp[w2];
                t[cl][w2 + 32] = xp[w2 + 32];
            }
            if (tid < 32) sv[tid] = g_s[b * CIN + ci0 + tid];
        }
        __syncthreads();
        int ci = tid & 31, wg = tid >> 5;
        float s = sv[ci];
#pragma unroll
        for (int ww = 0; ww < 8; ww++) {
            int w = wg * 8 + ww;
            size_t base = (((size_t)b * 66 + h + 1) * 66 + (w + 1)) * 512 + ci0 + ci;
            g_xcat[base] = to_tf32(t[ci][w] * s);
        }
    }
}

// ---------------------------------------------------------------------------
// Kernel 5: tf32 HMMA conv.  Per CTA: M=co(128), N=spatial(256 = 4h x 64w).
// 8 warps (4 co x 2 h-pairs), warp tile 32co x 128sp.
// Stage = 16-ci chunk: 32 stages, single pass.  Smem rows 64B (16 tf32),
// XOR swizzle on 16B chunks.  A: 9 offs x 128co x 64B; B patch: 6x66 x 64B.
// 2-slot rings, 1 commit group per stage.
// ---------------------------------------------------------------------------
#define NSTG    32
#define A_BYTES (9 * 128 * 64)          /* 73728 per A slot */
#define P_BYTES (6 * 66 * 64)           /* 25344 per B slot */
#define SMEM_SZ (2 * A_BYTES + 2 * P_BYTES)   /* 198144 */

__global__ __launch_bounds__(256, 1) void k_conv_mma(float* __restrict__ out) {
    extern __shared__ char smem[];
    uint32_t sb = smem_u32(smem);
    uint32_t Bbase = sb + 2 * A_BYTES;

    int tid  = threadIdx.x;
    int lane = tid & 31;
    int warp = tid >> 5;
    int wm   = warp & 3;          // 0..3 -> co
    int wn   = warp >> 2;         // 0..1 -> h-row pair
    int mBase = wm * 32;

    int h0  = blockIdx.x * 4;     // 4 output h rows per CTA
    int co0 = blockIdx.y * 128;
    int b   = blockIdx.z;

    const char* xb = (const char*)g_xcat;
    const char* wb = (const char*)g_wcat;

    float acc[2][16][4];          // [mt][hr*8 + pair*2 + half][frag]
#pragma unroll
    for (int i = 0; i < 2; i++)
#pragma unroll
        for (int j = 0; j < 16; j++)
#pragma unroll
            for (int k = 0; k < 4; k++) acc[i][j][k] = 0.f;

    // ---- stage loader: 16-ci chunk cc = st ----
    auto load_stage = [&](int st) {
        int cc = st;              // ci chunk of 16
        uint32_t As = sb + (st & 1) * A_BYTES;
        uint32_t Bp = Bbase + (st & 1) * P_BYTES;
        // A: 9 offsets x 128 co rows x 4 chunks of 16B
#pragma unroll
        for (int i = tid; i < 9 * 128 * 4; i += 256) {
            int o  = i >> 9;
            int rr = (i >> 2) & 127;
            int c  = i & 3;
            size_t off = (((size_t)o * COUT + co0 + rr) * 512 + cc * 16 + c * 4) * 4;
            cpa16(As + o * 8192 + (uint32_t)(rr * 64 + (((c ^ ((rr >> 1) & 3)) & 3) << 4)),
                  wb + off);
        }
        // B patch: 6 x 66 positions x 4 chunks
        for (int i = tid; i < 6 * 66 * 4; i += 256) {
            int pi = i >> 2;
            int c  = i & 3;
            int ph = pi / 66, pw = pi - ph * 66;
            size_t off = ((((size_t)b * 66 + h0 + ph) * 66 + pw) * 512 + cc * 16 + c * 4) * 4;
            cpa16(Bp + (uint32_t)(pi * 64 + (((c ^ ((pi >> 1) & 3)) & 3) << 4)),
                  xb + off);
        }
        CP_COMMIT();
    };

    load_stage(0);
    load_stage(1);

    // per-lane fragment addressing
    int aR0  = mBase + (lane & 15);              // A row (+ mt*16)
    int aSel = (aR0 >> 1) & 3;
    int acL  = lane >> 4;                        // 0..1 (chunk within k8 pair)
    int nLane = (lane & 7) + ((lane >> 4) << 3); // B row offset within 16-group
    int cbL   = (lane >> 3) & 1;                 // B chunk within k8 pair

    for (int st = 0; st < NSTG; st++) {
        if (st == NSTG - 1) cp_wait<0>(); else cp_wait<1>();
        __syncthreads();

        uint32_t As = sb + (st & 1) * A_BYTES;
        uint32_t Bp = Bbase + (st & 1) * P_BYTES;

#pragma unroll
        for (int ky = 0; ky < 3; ky++) {
#pragma unroll
            for (int kx = 0; kx < 3; kx++) {
                uint32_t Ao = As + (ky * 3 + kx) * 8192;
#pragma unroll
                for (int k8 = 0; k8 < 2; k8++) {
                    int ca = 2 * k8 + acL;
                    uint32_t a[2][4];
#pragma unroll
                    for (int mt = 0; mt < 2; mt++) {
                        int row = aR0 + mt * 16;
                        ldsm4(a[mt], Ao + (uint32_t)(row * 64 +
                              (((ca ^ ((row >> 1) & 3)) & 3) << 4)));
                    }
                    int cb = 2 * k8 + cbL;
#pragma unroll
                    for (int hr = 0; hr < 2; hr++) {
                        int q0 = (2 * wn + hr + ky) * 66 + kx + nLane;
#pragma unroll
                        for (int pair = 0; pair < 4; pair++) {
                            int row = q0 + pair * 16;
                            uint32_t bf[4];
                            ldsm4(bf, Bp + (uint32_t)(row * 64 +
                                  (((cb ^ ((row >> 1) & 3)) & 3) << 4)));
#pragma unroll
                            for (int mt = 0; mt < 2; mt++) {
                                mma1688(acc[mt][hr * 8 + pair * 2 + 0], a[mt], bf[0], bf[1]);
                                mma1688(acc[mt][hr * 8 + pair * 2 + 1], a[mt], bf[2], bf[3]);
                            }
                        }
                    }
                }
            }
        }

        __syncthreads();
        if (st + 2 < NSTG) load_stage(st + 2);
    }

    // ---- epilogue: demod scale + float2 stores ----
#pragma unroll
    for (int mt = 0; mt < 2; mt++) {
#pragma unroll
        for (int r = 0; r < 2; r++) {
            int co = co0 + mBase + mt * 16 + (lane >> 2) + r * 8;
            float dm = g_demod[b * COUT + co];
            float* op = out + (((size_t)b * COUT + co) << 12);
#pragma unroll
            for (int hr = 0; hr < 2; hr++) {
                int h = h0 + 2 * wn + hr;
#pragma unroll
                for (int j = 0; j < 8; j++) {
                    int n = (j >> 1) * 16 + (j & 1) * 8 + 2 * (lane & 3);
                    float2 v;
                    v.x = acc[mt][hr * 8 + j][r * 2 + 0] * dm;
                    v.y = acc[mt][hr * 8 + j][r * 2 + 1] * dm;
                    *(float2*)(op + h * 64 + n) = v;
                }
            }
        }
    }
}

// ---------------------------------------------------------------------------
extern "C" void kernel_launch(void* const* d_in, const int* in_sizes, int n_in,
                              void* d_out, int out_size) {
    const float* x      = (const float*)d_in[0];  // [16,512,64,64]
    const float* style  = (const float*)d_in[1];  // [16,512]
    const float* weight = (const float*)d_in[2];  // [1,512,512,3,3]
    const float* mw     = (const float*)d_in[3];  // [512,512]
    const float* mb     = (const float*)d_in[4];  // [512]
    float* out          = (float*)d_out;          // [16,512,64,64]

    k_style<<<BB, SDIM>>>(style, mw, mb);
    k_prepw<<<COUT, CIN>>>(weight);
    k_demod<<<COUT, 256>>>(weight);
    {
        dim3 g(HH, BB);
        k_prepx<<<g, 256>>>(x);
    }
    cudaFuncSetAttribute(k_conv_mma, cudaFuncAttributeMaxDynamicSharedMemorySize, SMEM_SZ);
    {
        dim3 g(16 /*spatial tiles*/, 4 /*co tiles*/, BB);
        k_conv_mma<<<g, 256, SMEM_SZ>>>(out);
    }
}

// round 12
// speedup vs baseline: 8.6183x; 1.0229x over previous
#include <cuda_runtime.h>
#include <cuda_bf16.h>
#include <cstdint>

#define BB   16
#define CIN  512
#define COUT 512
#define HH   64
#define WW   64
#define SDIM 512

#define CONV_SCALE 0.014731391274719737f   /* 1/sqrt(512*9) */
#define MOD_SCALE  0.04419417382415922f    /* 1/sqrt(512)   */
#define EPS        1e-8f

// ---------------------------------------------------------------------------
// Device scratch (allocation-free rule: __device__ globals, zero-initialized)
// ---------------------------------------------------------------------------
__device__ float g_s[BB * CIN];
__device__ float g_demod[BB * COUT];
// Padded NHWC modulated input, tf32-rounded fp32: [b][66][66][ci:512]
// Borders (row/col 0 and 65) never written -> stay zero (static zero-init).
__device__ float g_xcat[(size_t)BB * 66 * 66 * 512];
// Weights tf32-rounded fp32: [k(9)][co(512)][ci(512)], pre-scaled by CONV_SCALE
__device__ float g_wcat[(size_t)9 * COUT * CIN];

// ---------------------------------------------------------------------------
// PTX helpers (base ISA only: cp.async / ldmatrix / mma.sync tf32)
// ---------------------------------------------------------------------------
__device__ __forceinline__ uint32_t smem_u32(const void* p) {
    uint32_t a;
    asm("{ .reg .u64 t; cvta.to.shared.u64 t, %1; cvt.u32.u64 %0, t; }" : "=r"(a) : "l"(p));
    return a;
}
__device__ __forceinline__ void cpa16(uint32_t dst, const void* src) {
    asm volatile("cp.async.cg.shared.global [%0], [%1], 16;" :: "r"(dst), "l"(src));
}
#define CP_COMMIT() asm volatile("cp.async.commit_group;" ::: "memory")
template <int N>
__device__ __forceinline__ void cp_wait() {
    asm volatile("cp.async.wait_group %0;" :: "n"(N) : "memory");
}
__device__ __forceinline__ void ldsm4(uint32_t* r, uint32_t addr) {
    asm volatile("ldmatrix.sync.aligned.m8n8.x4.shared.b16 {%0,%1,%2,%3}, [%4];"
                 : "=r"(r[0]), "=r"(r[1]), "=r"(r[2]), "=r"(r[3]) : "r"(addr));
}
// tf32 mma: D(16x8) += A(16x8) * B(8x8); A,B are 32-bit tf32 regs
__device__ __forceinline__ void mma1688(float* d, const uint32_t* a,
                                        uint32_t b0, uint32_t b1) {
    asm volatile(
        "mma.sync.aligned.m16n8k8.row.col.f32.tf32.tf32.f32 "
        "{%0,%1,%2,%3}, {%4,%5,%6,%7}, {%8,%9}, {%0,%1,%2,%3};"
        : "+f"(d[0]), "+f"(d[1]), "+f"(d[2]), "+f"(d[3])
        : "r"(a[0]), "r"(a[1]), "r"(a[2]), "r"(a[3]), "r"(b0), "r"(b1));
}
__device__ __forceinline__ float to_tf32(float v) {
    uint32_t r;
    asm("cvt.rna.tf32.f32 %0, %1;" : "=r"(r) : "f"(v));
    return __uint_as_float(r);
}

// ---------------------------------------------------------------------------
// Kernel 1: modulation scales
// ---------------------------------------------------------------------------
__global__ void k_style(const float* __restrict__ style,
                        const float* __restrict__ mw,
                        const float* __restrict__ mb) {
    __shared__ float st[SDIM];
    int b = blockIdx.x;
    int t = threadIdx.x;
    st[t] = style[b * SDIM + t];
    __syncthreads();
    const float4* wrow = (const float4*)(mw + (size_t)t * SDIM);
    const float4* srow = (const float4*)st;
    float acc = 0.f;
#pragma unroll 8
    for (int j = 0; j < SDIM / 4; j++) {
        float4 w4 = wrow[j];
        float4 s4 = srow[j];
        acc += w4.x * s4.x + w4.y * s4.y + w4.z * s4.z + w4.w * s4.w;
    }
    g_s[b * CIN + t] = acc * MOD_SCALE + mb[t];
}

// ---------------------------------------------------------------------------
// Kernel 2: demod[b][co]  (exact fp32 weights -- matches reference)
// ---------------------------------------------------------------------------
__global__ void k_demod(const float* __restrict__ w) {
    int co = blockIdx.x;
    int t  = threadIdx.x;
    float acc[BB];
#pragma unroll
    for (int b = 0; b < BB; b++) acc[b] = 0.f;

    for (int ci = t; ci < CIN; ci += 256) {
        const float* wp = w + ((size_t)co * CIN + ci) * 9;
        float wsq = 0.f;
#pragma unroll
        for (int i = 0; i < 9; i++) wsq += wp[i] * wp[i];
#pragma unroll
        for (int b = 0; b < BB; b++) {
            float sv = g_s[b * CIN + ci];
            acc[b] += wsq * sv * sv;
        }
    }

    __shared__ float red[BB][257];
#pragma unroll
    for (int b = 0; b < BB; b++) red[b][t] = acc[b];
    __syncthreads();
    for (int off = 128; off > 0; off >>= 1) {
        if (t < off) {
#pragma unroll
            for (int b = 0; b < BB; b++) red[b][t] += red[b][t + off];
        }
        __syncthreads();
    }
    if (t < BB) {
        float v = red[t][0];
        g_demod[t * COUT + co] = rsqrtf(CONV_SCALE * CONV_SCALE * v + EPS);
    }
}

// ---------------------------------------------------------------------------
// Kernel 3: weights -> tf32-rounded, [k][co][ci], pre-scaled
// ---------------------------------------------------------------------------
__global__ void k_prepw(const float* __restrict__ wt) {
    int co = blockIdx.x, ci = threadIdx.x;
    const float* wp = wt + ((size_t)co * CIN + ci) * 9;
#pragma unroll
    for (int k = 0; k < 9; k++) {
        g_wcat[((size_t)k * COUT + co) * CIN + ci] = to_tf32(CONV_SCALE * wp[k]);
    }
}

// ---------------------------------------------------------------------------
// Kernel 4: x -> modulated padded NHWC tf32-rounded
// ---------------------------------------------------------------------------
__global__ void k_prepx(const float* __restrict__ x) {
    int h = blockIdx.x, b = blockIdx.y;
    int tid = threadIdx.x;
    __shared__ float t[32][65];
    __shared__ float sv[32];
    for (int chunk = 0; chunk < 16; chunk++) {
        int ci0 = chunk * 32;
        __syncthreads();
        {
            int r  = tid >> 5;
            int w2 = tid & 31;
#pragma unroll
            for (int rr = 0; rr < 4; rr++) {
                int cl = r * 4 + rr;
                const float* xp = x + (((size_t)b * CIN + ci0 + cl) * HH + h) * WW;
                t[cl][w2]      = xp[w2];
                t[cl][w2 + 32] = xp[w2 + 32];
            }
            if (tid < 32) sv[tid] = g_s[b * CIN + ci0 + tid];
        }
        __syncthreads();
        int ci = tid & 31, wg = tid >> 5;
        float s = sv[ci];
#pragma unroll
        for (int ww = 0; ww < 8; ww++) {
            int w = wg * 8 + ww;
            size_t base = (((size_t)b * 66 + h + 1) * 66 + (w + 1)) * 512 + ci0 + ci;
            g_xcat[base] = to_tf32(t[ci][w] * s);
        }
    }
}

// ---------------------------------------------------------------------------
// Kernel 5: tf32 HMMA conv.  Per CTA: M=co(128), N=spatial(256 = 4h x 64w).
// 8 warps (4 co x 2 h-pairs), warp tile 32co x 128sp.
// Stage = 8-ci chunk: 64 stages.  Smem rows 32B (8 tf32), XOR swizzle
// (chunk ^ ((row>>2)&1)) on 16B units -- conflict-free for any base row.
// A: 9 offs x 128co x 32B (36864B/slot); B patch: 6x66 x 32B (12672B/slot).
// 4-slot rings, 3-deep prefetch, ONE barrier per stage.
// ---------------------------------------------------------------------------
#define NSTG    64
#define A_SLOT  36864
#define B_SLOT  12672
#define B_BASE  (4 * A_SLOT)                     /* 147456 */
#define SMEM_SZ (4 * A_SLOT + 4 * B_SLOT)        /* 198144 */

__global__ __launch_bounds__(256, 1) void k_conv_mma(float* __restrict__ out) {
    extern __shared__ char smem[];
    uint32_t sb = smem_u32(smem);

    int tid  = threadIdx.x;
    int lane = tid & 31;
    int warp = tid >> 5;
    int wm   = warp & 3;          // 0..3 -> co
    int wn   = warp >> 2;         // 0..1 -> h-row pair
    int mBase = wm * 32;

    int h0  = blockIdx.x * 4;     // 4 output h rows per CTA
    int co0 = blockIdx.y * 128;
    int b   = blockIdx.z;

    const char* xb = (const char*)g_xcat;
    const char* wb = (const char*)g_wcat;

    float acc[2][16][4];          // [mt][hr*8 + pair*2 + half][frag]
#pragma unroll
    for (int i = 0; i < 2; i++)
#pragma unroll
        for (int j = 0; j < 16; j++)
#pragma unroll
            for (int k = 0; k < 4; k++) acc[i][j][k] = 0.f;

    // ---- stage loader: 8-ci chunk cc = st ----
    auto load_stage = [&](int st) {
        int slot = st & 3;
        uint32_t As = sb + slot * A_SLOT;
        uint32_t Bp = sb + B_BASE + slot * B_SLOT;
        // A: 9 offsets x 128 co rows x 2 chunks of 16B  (2304 -> 9/thread)
#pragma unroll
        for (int i = tid; i < 9 * 128 * 2; i += 256) {
            int o  = i >> 8;
            int rr = (i >> 1) & 127;
            int c  = i & 1;
            size_t off = (((size_t)o * COUT + co0 + rr) * 512 + st * 8 + c * 4) * 4;
            cpa16(As + o * 4096 + (uint32_t)(rr * 32 + (((c ^ ((rr >> 2) & 1)) & 1) << 4)),
                  wb + off);
        }
        // B patch: 6 x 66 positions x 2 chunks (792)
        for (int i = tid; i < 6 * 66 * 2; i += 256) {
            int pi = i >> 1;
            int c  = i & 1;
            int ph = pi / 66, pw = pi - ph * 66;
            size_t off = ((((size_t)b * 66 + h0 + ph) * 66 + pw) * 512 + st * 8 + c * 4) * 4;
            cpa16(Bp + (uint32_t)(pi * 32 + (((c ^ ((pi >> 2) & 1)) & 1) << 4)),
                  xb + off);
        }
        CP_COMMIT();
    };

    load_stage(0);
    load_stage(1);
    load_stage(2);

    // per-lane fragment addressing
    int aR0  = mBase + (lane & 15);              // A row (+ mt*16)
    int acL  = lane >> 4;                        // 0..1 chunk (k half)
    uint32_t aOff = (uint32_t)(((acL ^ ((aR0 >> 2) & 1)) & 1) << 4);  // invariant in mt
    int nLane = (lane & 7) + ((lane >> 4) << 3); // B row offset within 16-group
    int cbL   = (lane >> 3) & 1;                 // B chunk (k half)

    for (int st = 0; st < NSTG; st++) {
        if (st <= NSTG - 3) cp_wait<2>();
        else if (st == NSTG - 2) cp_wait<1>();
        else cp_wait<0>();
        __syncthreads();   // single barrier per stage (safe with 4-slot ring)

        uint32_t As = sb + (st & 3) * A_SLOT;
        uint32_t Bp = sb + B_BASE + (st & 3) * B_SLOT;

#pragma unroll
        for (int ky = 0; ky < 3; ky++) {
#pragma unroll
            for (int kx = 0; kx < 3; kx++) {
                uint32_t Ao = As + (ky * 3 + kx) * 4096;
                uint32_t a[2][4];
#pragma unroll
                for (int mt = 0; mt < 2; mt++)
                    ldsm4(a[mt], Ao + (uint32_t)((aR0 + mt * 16) * 32) + aOff);
#pragma unroll
                for (int hr = 0; hr < 2; hr++) {
                    int q0 = (2 * wn + hr + ky) * 66 + kx + nLane;
                    uint32_t bOff = (uint32_t)(((cbL ^ ((q0 >> 2) & 1)) & 1) << 4);
                    uint32_t Bq = Bp + (uint32_t)(q0 * 32) + bOff;
#pragma unroll
                    for (int pair = 0; pair < 4; pair++) {
                        uint32_t bf[4];
                        ldsm4(bf, Bq + (uint32_t)(pair * 512));
#pragma unroll
                        for (int mt = 0; mt < 2; mt++) {
                            mma1688(acc[mt][hr * 8 + pair * 2 + 0], a[mt], bf[0], bf[1]);
                            mma1688(acc[mt][hr * 8 + pair * 2 + 1], a[mt], bf[2], bf[3]);
                        }
                    }
                }
            }
        }

        if (st + 3 < NSTG) load_stage(st + 3);
    }

    // ---- epilogue: demod scale + float2 stores ----
#pragma unroll
    for (int mt = 0; mt < 2; mt++) {
#pragma unroll
        for (int r = 0; r < 2; r++) {
            int co = co0 + mBase + mt * 16 + (lane >> 2) + r * 8;
            float dm = g_demod[b * COUT + co];
            float* op = out + (((size_t)b * COUT + co) << 12);
#pragma unroll
            for (int hr = 0; hr < 2; hr++) {
                int h = h0 + 2 * wn + hr;
#pragma unroll
                for (int j = 0; j < 8; j++) {
                    int n = (j >> 1) * 16 + (j & 1) * 8 + 2 * (lane & 3);
                    float2 v;
                    v.x = acc[mt][hr * 8 + j][r * 2 + 0] * dm;
                    v.y = acc[mt][hr * 8 + j][r * 2 + 1] * dm;
                    *(float2*)(op + h * 64 + n) = v;
                }
            }
        }
    }
}

// ---------------------------------------------------------------------------
extern "C" void kernel_launch(void* const* d_in, const int* in_sizes, int n_in,
                              void* d_out, int out_size) {
    const float* x      = (const float*)d_in[0];  // [16,512,64,64]
    const float* style  = (const float*)d_in[1];  // [16,512]
    const float* weight = (const float*)d_in[2];  // [1,512,512,3,3]
    const float* mw     = (const float*)d_in[3];  // [512,512]
    const float* mb     = (const float*)d_in[4];  // [512]
    float* out          = (float*)d_out;          // [16,512,64,64]

    k_style<<<BB, SDIM>>>(style, mw, mb);
    k_prepw<<<COUT, CIN>>>(weight);
    k_demod<<<COUT, 256>>>(weight);
    {
        dim3 g(HH, BB);
        k_prepx<<<g, 256>>>(x);
    }
    cudaFuncSetAttribute(k_conv_mma, cudaFuncAttributeMaxDynamicSharedMemorySize, SMEM_SZ);
    {
        dim3 g(16 /*spatial tiles*/, 4 /*co tiles*/, BB);
        k_conv_mma<<<g, 256, SMEM_SZ>>>(out);
    }
}

// round 15
// speedup vs baseline: 8.8279x; 1.0243x over previous
#include <cuda_runtime.h>
#include <cuda_bf16.h>
#include <cstdint>

#define BB   16
#define CIN  512
#define COUT 512
#define HH   64
#define WW   64
#define SDIM 512

#define CONV_SCALE 0.014731391274719737f   /* 1/sqrt(512*9) */
#define MOD_SCALE  0.04419417382415922f    /* 1/sqrt(512)   */
#define EPS        1e-8f

// ---------------------------------------------------------------------------
// Device scratch (allocation-free rule: __device__ globals, zero-initialized)
// ---------------------------------------------------------------------------
__device__ float g_s[BB * CIN];
__device__ float g_demod[BB * COUT];
// Padded NHWC modulated input, tf32-rounded fp32: [b][66][66][ci:512]
__device__ float g_xcat[(size_t)BB * 66 * 66 * 512];
// Weights tf32-rounded fp32: [k(9)][co(512)][ci(512)], pre-scaled
__device__ float g_wcat[(size_t)9 * COUT * CIN];

// ---------------------------------------------------------------------------
// PTX helpers (base ISA only)
// ---------------------------------------------------------------------------
__device__ __forceinline__ uint32_t smem_u32(const void* p) {
    uint32_t a;
    asm("{ .reg .u64 t; cvta.to.shared.u64 t, %1; cvt.u32.u64 %0, t; }" : "=r"(a) : "l"(p));
    return a;
}
__device__ __forceinline__ void cpa16(uint32_t dst, const void* src) {
    asm volatile("cp.async.cg.shared.global [%0], [%1], 16;" :: "r"(dst), "l"(src));
}
#define CP_COMMIT() asm volatile("cp.async.commit_group;" ::: "memory")
template <int N>
__device__ __forceinline__ void cp_wait() {
    asm volatile("cp.async.wait_group %0;" :: "n"(N) : "memory");
}
__device__ __forceinline__ void ldsm4(uint32_t* r, uint32_t addr) {
    asm volatile("ldmatrix.sync.aligned.m8n8.x4.shared.b16 {%0,%1,%2,%3}, [%4];"
                 : "=r"(r[0]), "=r"(r[1]), "=r"(r[2]), "=r"(r[3]) : "r"(addr));
}
__device__ __forceinline__ void mma1688(float* d, const uint32_t* a,
                                        uint32_t b0, uint32_t b1) {
    asm volatile(
        "mma.sync.aligned.m16n8k8.row.col.f32.tf32.tf32.f32 "
        "{%0,%1,%2,%3}, {%4,%5,%6,%7}, {%8,%9}, {%0,%1,%2,%3};"
        : "+f"(d[0]), "+f"(d[1]), "+f"(d[2]), "+f"(d[3])
        : "r"(a[0]), "r"(a[1]), "r"(a[2]), "r"(a[3]), "r"(b0), "r"(b1));
}
__device__ __forceinline__ float to_tf32(float v) {
    uint32_t r;
    asm("cvt.rna.tf32.f32 %0, %1;" : "=r"(r) : "f"(v));
    return __uint_as_float(r);
}

// ---------------------------------------------------------------------------
// Kernel 1: modulation scales
// ---------------------------------------------------------------------------
__global__ void k_style(const float* __restrict__ style,
                        const float* __restrict__ mw,
                        const float* __restrict__ mb) {
    __shared__ float st[SDIM];
    int b = blockIdx.x;
    int t = threadIdx.x;
    st[t] = style[b * SDIM + t];
    __syncthreads();
    const float4* wrow = (const float4*)(mw + (size_t)t * SDIM);
    const float4* srow = (const float4*)st;
    float acc = 0.f;
#pragma unroll 8
    for (int j = 0; j < SDIM / 4; j++) {
        float4 w4 = wrow[j];
        float4 s4 = srow[j];
        acc += w4.x * s4.x + w4.y * s4.y + w4.z * s4.z + w4.w * s4.w;
    }
    g_s[b * CIN + t] = acc * MOD_SCALE + mb[t];
}

// ---------------------------------------------------------------------------
// Kernel 2: demod[b][co]
// ---------------------------------------------------------------------------
__global__ void k_demod(const float* __restrict__ w) {
    int co = blockIdx.x;
    int t  = threadIdx.x;
    float acc[BB];
#pragma unroll
    for (int b = 0; b < BB; b++) acc[b] = 0.f;

    for (int ci = t; ci < CIN; ci += 256) {
        const float* wp = w + ((size_t)co * CIN + ci) * 9;
        float wsq = 0.f;
#pragma unroll
        for (int i = 0; i < 9; i++) wsq += wp[i] * wp[i];
#pragma unroll
        for (int b = 0; b < BB; b++) {
            float sv = g_s[b * CIN + ci];
            acc[b] += wsq * sv * sv;
        }
    }

    __shared__ float red[BB][257];
#pragma unroll
    for (int b = 0; b < BB; b++) red[b][t] = acc[b];
    __syncthreads();
    for (int off = 128; off > 0; off >>= 1) {
        if (t < off) {
#pragma unroll
            for (int b = 0; b < BB; b++) red[b][t] += red[b][t + off];
        }
        __syncthreads();
    }
    if (t < BB) {
        float v = red[t][0];
        g_demod[t * COUT + co] = rsqrtf(CONV_SCALE * CONV_SCALE * v + EPS);
    }
}

// ---------------------------------------------------------------------------
// Kernel 3: weights -> tf32-rounded, [k][co][ci], pre-scaled
// ---------------------------------------------------------------------------
__global__ void k_prepw(const float* __restrict__ wt) {
    int co = blockIdx.x, ci = threadIdx.x;
    const float* wp = wt + ((size_t)co * CIN + ci) * 9;
#pragma unroll
    for (int k = 0; k < 9; k++) {
        g_wcat[((size_t)k * COUT + co) * CIN + ci] = to_tf32(CONV_SCALE * wp[k]);
    }
}

// ---------------------------------------------------------------------------
// Kernel 4: x -> modulated padded NHWC tf32-rounded
// ---------------------------------------------------------------------------
__global__ void k_prepx(const float* __restrict__ x) {
    int h = blockIdx.x, b = blockIdx.y;
    int tid = threadIdx.x;
    __shared__ float t[32][65];
    __shared__ float sv[32];
    for (int chunk = 0; chunk < 16; chunk++) {
        int ci0 = chunk * 32;
        __syncthreads();
        {
            int r  = tid >> 5;
            int w2 = tid & 31;
#pragma unroll
            for (int rr = 0; rr < 4; rr++) {
                int cl = r * 4 + rr;
                const float* xp = x + (((size_t)b * CIN + ci0 + cl) * HH + h) * WW;
                t[cl][w2]      = xp[w2];
                t[cl][w2 + 32] = xp[w2 + 32];
            }
            if (tid < 32) sv[tid] = g_s[b * CIN + ci0 + tid];
        }
        __syncthreads();
        int ci = tid & 31, wg = tid >> 5;
        float s = sv[ci];
#pragma unroll
        for (int ww = 0; ww < 8; ww++) {
            int w = wg * 8 + ww;
            size_t base = (((size_t)b * 66 + h + 1) * 66 + (w + 1)) * 512 + ci0 + ci;
            g_xcat[base] = to_tf32(t[ci][w] * s);
        }
    }
}

// ---------------------------------------------------------------------------
// Kernel 5: tf32 HMMA conv with (hr,ky)-diagonal B-fragment sharing.
// Per CTA: M=co(128), N=spatial(256 = 4h x 64w).  8 warps (4co x 2h-pairs).
// Per stage (8-ci chunk): for each kx, A frags for all 3 ky loaded once
// (6 ldsm), then per pair-column the 4 DISTINCT B patch rows (2wn+r, r=0..3)
// loaded once (4 ldsm) and reused for all (hr,ky) with hr+ky==r.
// ldsm/warp/stage: 90 -> 66 (smem-read per MMA 160B -> 117B).
// 4-slot rings, 3-deep prefetch, one barrier per stage.
// ---------------------------------------------------------------------------
#define NSTG    64
#define A_SLOT  36864
#define B_SLOT  12672
#define B_BASE  (4 * A_SLOT)
#define SMEM_SZ (4 * A_SLOT + 4 * B_SLOT)        /* 198144 */

__global__ __launch_bounds__(256, 1) void k_conv_mma(float* __restrict__ out) {
    extern __shared__ char smem[];
    uint32_t sb = smem_u32(smem);

    int tid  = threadIdx.x;
    int lane = tid & 31;
    int warp = tid >> 5;
    int wm   = warp & 3;          // 0..3 -> co
    int wn   = warp >> 2;         // 0..1 -> h-row pair
    int mBase = wm * 32;

    int h0  = blockIdx.x * 4;
    int co0 = blockIdx.y * 128;
    int b   = blockIdx.z;

    const char* xb = (const char*)g_xcat;
    const char* wb = (const char*)g_wcat;

    float acc[2][16][4];          // [mt][hr*8 + pair*2 + half][frag]
#pragma unroll
    for (int i = 0; i < 2; i++)
#pragma unroll
        for (int j = 0; j < 16; j++)
#pragma unroll
            for (int k = 0; k < 4; k++) acc[i][j][k] = 0.f;

    // ---- stage loader: 8-ci chunk cc = st ----
    auto load_stage = [&](int st) {
        int slot = st & 3;
        uint32_t As = sb + slot * A_SLOT;
        uint32_t Bp = sb + B_BASE + slot * B_SLOT;
#pragma unroll
        for (int i = tid; i < 9 * 128 * 2; i += 256) {
            int o  = i >> 8;
            int rr = (i >> 1) & 127;
            int c  = i & 1;
            size_t off = (((size_t)o * COUT + co0 + rr) * 512 + st * 8 + c * 4) * 4;
            cpa16(As + o * 4096 + (uint32_t)(rr * 32 + (((c ^ ((rr >> 2) & 1)) & 1) << 4)),
                  wb + off);
        }
        for (int i = tid; i < 6 * 66 * 2; i += 256) {
            int pi = i >> 1;
            int c  = i & 1;
            int ph = pi / 66, pw = pi - ph * 66;
            size_t off = ((((size_t)b * 66 + h0 + ph) * 66 + pw) * 512 + st * 8 + c * 4) * 4;
            cpa16(Bp + (uint32_t)(pi * 32 + (((c ^ ((pi >> 2) & 1)) & 1) << 4)),
                  xb + off);
        }
        CP_COMMIT();
    };

    load_stage(0);
    load_stage(1);
    load_stage(2);

    // per-lane fragment addressing
    int aR0  = mBase + (lane & 15);
    int acL  = lane >> 4;
    uint32_t aOff = (uint32_t)(((acL ^ ((aR0 >> 2) & 1)) & 1) << 4);  // invariant in mt
    int nLane = (lane & 7) + ((lane >> 4) << 3);
    int cbL   = (lane >> 3) & 1;

    for (int st = 0; st < NSTG; st++) {
        if (st <= NSTG - 3) cp_wait<2>();
        else if (st == NSTG - 2) cp_wait<1>();
        else cp_wait<0>();
        __syncthreads();

        uint32_t As = sb + (st & 3) * A_SLOT;
        uint32_t Bp = sb + B_BASE + (st & 3) * B_SLOT;

#pragma unroll
        for (int kx = 0; kx < 3; kx++) {
            // A fragments for all 3 ky at this kx
            uint32_t a[3][2][4];
#pragma unroll
            for (int ky = 0; ky < 3; ky++) {
                uint32_t Ao = As + (ky * 3 + kx) * 4096;
#pragma unroll
                for (int mt = 0; mt < 2; mt++)
                    ldsm4(a[ky][mt], Ao + (uint32_t)((aR0 + mt * 16) * 32) + aOff);
            }
            // B rows r = hr+ky in 0..3, loaded once per pair-column
#pragma unroll
            for (int pair = 0; pair < 4; pair++) {
                uint32_t bf[4][4];
#pragma unroll
                for (int r = 0; r < 4; r++) {
                    int q = (2 * wn + r) * 66 + kx + nLane + pair * 16;
                    uint32_t bOff = (uint32_t)(((cbL ^ ((q >> 2) & 1)) & 1) << 4);
                    ldsm4(bf[r], Bp + (uint32_t)(q * 32) + bOff);
                }
#pragma unroll
                for (int ky = 0; ky < 3; ky++)
#pragma unroll
                    for (int hr = 0; hr < 2; hr++) {
                        const uint32_t* bfr = bf[hr + ky];
#pragma unroll
                        for (int mt = 0; mt < 2; mt++) {
                            mma1688(acc[mt][hr * 8 + pair * 2 + 0], a[ky][mt], bfr[0], bfr[1]);
                            mma1688(acc[mt][hr * 8 + pair * 2 + 1], a[ky][mt], bfr[2], bfr[3]);
                        }
                    }
            }
        }

        if (st + 3 < NSTG) load_stage(st + 3);
    }

    // ---- epilogue: demod scale + float2 stores ----
#pragma unroll
    for (int mt = 0; mt < 2; mt++) {
#pragma unroll
        for (int r = 0; r < 2; r++) {
            int co = co0 + mBase + mt * 16 + (lane >> 2) + r * 8;
            float dm = g_demod[b * COUT + co];
            float* op = out + (((size_t)b * COUT + co) << 12);
#pragma unroll
            for (int hr = 0; hr < 2; hr++) {
                int h = h0 + 2 * wn + hr;
#pragma unroll
                for (int j = 0; j < 8; j++) {
                    int n = (j >> 1) * 16 + (j & 1) * 8 + 2 * (lane & 3);
                    float2 v;
                    v.x = acc[mt][hr * 8 + j][r * 2 + 0] * dm;
                    v.y = acc[mt][hr * 8 + j][r * 2 + 1] * dm;
                    *(float2*)(op + h * 64 + n) = v;
                }
            }
        }
    }
}

// ---------------------------------------------------------------------------
extern "C" void kernel_launch(void* const* d_in, const int* in_sizes, int n_in,
                              void* d_out, int out_size) {
    const float* x      = (const float*)d_in[0];  // [16,512,64,64]
    const float* style  = (const float*)d_in[1];  // [16,512]
    const float* weight = (const float*)d_in[2];  // [1,512,512,3,3]
    const float* mw     = (const float*)d_in[3];  // [512,512]
    const float* mb     = (const float*)d_in[4];  // [512]
    float* out          = (float*)d_out;          // [16,512,64,64]

    k_style<<<BB, SDIM>>>(style, mw, mb);
    k_prepw<<<COUT, CIN>>>(weight);
    k_demod<<<COUT, 256>>>(weight);
    {
        dim3 g(HH, BB);
        k_prepx<<<g, 256>>>(x);
    }
    cudaFuncSetAttribute(k_conv_mma, cudaFuncAttributeMaxDynamicSharedMemorySize, SMEM_SZ);
    {
        dim3 g(16 /*spatial tiles*/, 4 /*co tiles*/, BB);
        k_conv_mma<<<g, 256, SMEM_SZ>>>(out);
    }
}